// round 1
// baseline (speedup 1.0000x reference)
#include <cuda_runtime.h>
#include <cuda_bf16.h>
#include <stdint.h>

#define BB 2
#define SS 1024
#define DD 512
#define HH 8
#define DKK 64
#define RR 16
#define GG 2
#define GDD 32
#define NHH 4
#define KMAX 64
#define NEGF (-1e30f)

// ---------------- scratch (device globals; no allocation allowed) ----------
__device__ float g_qup[BB*HH*SS*DKK];   // [b][h][s][k]
__device__ float g_kup[BB*HH*SS*DKK];
__device__ float g_vup[BB*HH*SS*DKK];
__device__ float g_outh[BB*HH*SS*DKK];
__device__ unsigned g_hq[BB*HH*GG*SS];  // packed 4 hash bytes
__device__ unsigned g_hk[BB*HH*GG*SS];
__device__ unsigned g_qsign[HH*GG*SS];  // sign masks from batch B-1
__device__ unsigned g_ksign[HH*GG*SS];
__device__ int g_cand[BB*HH*SS*KMAX];

__device__ __forceinline__ unsigned f2u_ord(float f) {
    unsigned u = __float_as_uint(f);
    return (u & 0x80000000u) ? ~u : (u | 0x80000000u);
}

// ---------------- K1: low-rank q/k up-projections ---------------------------
// grid = B*S blocks, 256 threads
__global__ void k_projqk(const float* __restrict__ q, const float* __restrict__ k,
                         const float* __restrict__ Aq, const float* __restrict__ Bq,
                         const float* __restrict__ Ak, const float* __restrict__ Bk) {
    int bs = blockIdx.x;
    int b = bs >> 10, s = bs & (SS - 1);
    __shared__ float srow[2][DD];
    __shared__ float tmp[2][HH * RR];
    int tid = threadIdx.x;
    srow[0][tid]       = q[bs * DD + tid];
    srow[0][tid + 256] = q[bs * DD + tid + 256];
    srow[1][tid]       = k[bs * DD + tid];
    srow[1][tid + 256] = k[bs * DD + tid + 256];
    __syncthreads();
    {
        int which = tid >> 7;
        int t = tid & 127;
        int h = t >> 4, r = t & 15;
        const float* A = which ? Ak : Aq;
        const float* xr = srow[which];
        const float* ap = A + h * (DD * RR) + r;
        float acc = 0.f;
#pragma unroll 8
        for (int d = 0; d < DD; d++) acc += xr[d] * ap[d * RR];
        tmp[which][t] = acc;
    }
    __syncthreads();
    for (int which = 0; which < 2; which++) {
        const float* Bm = which ? Bk : Bq;
        float* outp = which ? g_kup : g_qup;
        for (int i = tid; i < HH * DKK; i += 256) {
            int h = i >> 6, kk = i & 63;
            float a = 0.f;
#pragma unroll
            for (int r = 0; r < RR; r++)
                a += tmp[which][h * RR + r] * Bm[h * RR * DKK + r * DKK + kk];
            outp[(((b * HH + h) * SS) + s) * DKK + kk] = a;
        }
    }
}

// ---------------- K2: v_up = value @ Wv (per head) --------------------------
// grid = (S/64, H, B), 256 threads, 64x64 tile, K-chunks of 32
__global__ void k_vup(const float* __restrict__ value, const float* __restrict__ Wv) {
    int s0 = blockIdx.x * 64;
    int h = blockIdx.y, b = blockIdx.z;
    __shared__ float As[64][32];
    __shared__ float Bs[32][64];
    int tid = threadIdx.x;
    int tx = tid & 15, ty = tid >> 4;
    float c[4][4] = {};
    for (int d0 = 0; d0 < DD; d0 += 32) {
        for (int i = tid; i < 64 * 32; i += 256) {
            int r = i >> 5, cc = i & 31;
            As[r][cc] = value[(b * SS + s0 + r) * DD + d0 + cc];
        }
        for (int i = tid; i < 32 * 64; i += 256) {
            int r = i >> 6, cc = i & 63;
            Bs[r][cc] = Wv[h * DD * DKK + (d0 + r) * DKK + cc];
        }
        __syncthreads();
#pragma unroll 8
        for (int d = 0; d < 32; d++) {
            float a0 = As[ty * 4 + 0][d];
            float a1 = As[ty * 4 + 1][d];
            float a2 = As[ty * 4 + 2][d];
            float a3 = As[ty * 4 + 3][d];
            float4 bv = *(const float4*)&Bs[d][tx * 4];
            c[0][0] += a0 * bv.x; c[0][1] += a0 * bv.y; c[0][2] += a0 * bv.z; c[0][3] += a0 * bv.w;
            c[1][0] += a1 * bv.x; c[1][1] += a1 * bv.y; c[1][2] += a1 * bv.z; c[1][3] += a1 * bv.w;
            c[2][0] += a2 * bv.x; c[2][1] += a2 * bv.y; c[2][2] += a2 * bv.z; c[2][3] += a2 * bv.w;
            c[3][0] += a3 * bv.x; c[3][1] += a3 * bv.y; c[3][2] += a3 * bv.z; c[3][3] += a3 * bv.w;
        }
        __syncthreads();
    }
    for (int i = 0; i < 4; i++) {
        int r = ty * 4 + i;
        float4 v = make_float4(c[i][0], c[i][1], c[i][2], c[i][3]);
        *(float4*)&g_vup[(((b * HH + h) * SS) + s0 + r) * DKK + tx * 4] = v;
    }
}

// ---------------- K3: LSH hashes + sign masks -------------------------------
// one thread per (b,h,g,s); grid 256 x 256
__global__ void k_hash(const float* __restrict__ lsh) {
    int idx = blockIdx.x * 256 + threadIdx.x;
    if (idx >= BB * HH * GG * SS) return;
    int s = idx & (SS - 1);
    int g = (idx >> 10) & 1;
    int h = (idx >> 11) & 7;
    int b = idx >> 14;
    const float* qr = &g_qup[(((b * HH + h) * SS) + s) * DKK + g * GDD];
    const float* kr = &g_kup[(((b * HH + h) * SS) + s) * DKK + g * GDD];
    const float* pp = &lsh[(h * GG + g) * GDD * NHH];
    float pq[NHH] = {}, pk[NHH] = {};
    unsigned sq = 0u, sk = 0u;
#pragma unroll 4
    for (int d = 0; d < GDD; d++) {
        float qv = qr[d], kv = kr[d];
        if (qv > 0.f) sq |= (1u << d);
        if (kv > 0.f) sk |= (1u << d);
#pragma unroll
        for (int n = 0; n < NHH; n++) {
            float w = pp[d * NHH + n];
            pq[n] += qv * w;
            pk[n] += kv * w;
        }
    }
    unsigned hq = 0u, hk = 0u;
#pragma unroll
    for (int n = 0; n < NHH; n++) {
        int fq = (int)floorf(pq[n] * 0.25f);
        int fk = (int)floorf(pk[n] * 0.25f);
        hq |= ((unsigned)(fq & 63)) << (8 * n);
        hk |= ((unsigned)(fk & 63)) << (8 * n);
    }
    g_hq[idx] = hq;
    g_hk[idx] = hk;
    if (b == BB - 1) {
        g_qsign[(h * GG + g) * SS + s] = sq;
        g_ksign[(h * GG + g) * SS + s] = sk;
    }
}

// ---------------- K4: candidate generation ----------------------------------
// one block (128 threads) per row (b,h,s)
__global__ void k_cand() {
    int row = blockIdx.x;              // (b*H+h)*S + s
    int s = row & (SS - 1);
    int h = (row >> 10) & 7;
    int b = row >> 13;
    __shared__ float sc[SS];
    __shared__ unsigned combw[32];
    __shared__ unsigned unionw[32];
    __shared__ float qrow[DKK];
    __shared__ int cnt;
    __shared__ unsigned sh_prefix;
    __shared__ int sh_kk, sh_cnt2;
    __shared__ int pref32[32];

    int tid = threadIdx.x;
    int lane = tid & 31;
    if (tid < DKK) qrow[tid] = g_qup[row * DKK + tid];
    if (tid < 32) unionw[tid] = 0u;
    __syncthreads();

    for (int g = 0; g < GG; g++) {
        if (tid == 0) cnt = 0;
        __syncthreads();
        unsigned qsig = g_qsign[(h * GG + g) * SS + s];
        unsigned hqp = g_hq[(((b * HH + h) * GG + g) * SS) + s];
        const unsigned* ksg = &g_ksign[(h * GG + g) * SS];
        const unsigned* hkp = &g_hk[(((b * HH + h) * GG + g) * SS)];
        const float* kbase = &g_kup[(b * HH + h) * SS * DKK + g * GDD];
        for (int jj = 0; jj < 8; jj++) {
            int j = jj * 128 + tid;
            bool comb = (ksg[j] == qsig) && (__vcmpeq4(hqp, hkp[j]) != 0u);
            float v = NEGF;
            if (comb) {
                const float* kr = kbase + j * DKK;
                float a = 0.f;
#pragma unroll
                for (int d = 0; d < GDD; d++) a += qrow[g * GDD + d] * kr[d];
                v = a;
            }
            sc[j] = v;
            unsigned m = __ballot_sync(0xffffffffu, comb);
            if (lane == 0) {
                combw[j >> 5] = m;
                if (m) atomicAdd(&cnt, __popc(m));
            }
        }
        __syncthreads();
        int c = cnt;
        unsigned thresh = 0u;
        bool useth = false;
        if (c > KMAX) {
            // exact radix-select: 64th largest of the 1024 masked scores
            if (tid == 0) { sh_prefix = 0u; sh_kk = KMAX; }
            __syncthreads();
            for (int bit = 31; bit >= 0; bit--) {
                if (tid == 0) sh_cnt2 = 0;
                __syncthreads();
                unsigned pref = sh_prefix;
                int local = 0;
                for (int jj = 0; jj < 8; jj++) {
                    int j = jj * 128 + tid;
                    unsigned key = f2u_ord(sc[j]);
                    unsigned hi = (bit == 31) ? 0u : (key >> (bit + 1));
                    if (hi == pref && ((key >> bit) & 1u)) local++;
                }
                local += __shfl_xor_sync(0xffffffffu, local, 16);
                local += __shfl_xor_sync(0xffffffffu, local, 8);
                local += __shfl_xor_sync(0xffffffffu, local, 4);
                local += __shfl_xor_sync(0xffffffffu, local, 2);
                local += __shfl_xor_sync(0xffffffffu, local, 1);
                if (lane == 0) atomicAdd(&sh_cnt2, local);
                __syncthreads();
                if (tid == 0) {
                    int cc = sh_cnt2;
                    if (cc >= sh_kk) sh_prefix = (sh_prefix << 1) | 1u;
                    else { sh_kk -= cc; sh_prefix = sh_prefix << 1; }
                }
                __syncthreads();
            }
            thresh = sh_prefix;
            useth = true;
        }
        __syncthreads();
        // selected -> union bitmask
        for (int jj = 0; jj < 8; jj++) {
            int j = jj * 128 + tid;
            bool sel = (combw[j >> 5] >> (j & 31)) & 1u;
            if (sel && useth) sel = (f2u_ord(sc[j]) >= thresh);
            unsigned m = __ballot_sync(0xffffffffu, sel);
            if (lane == 0) unionw[j >> 5] |= m;
        }
        __syncthreads();
    }
    // enumerate smallest 64 indices of union
    if (tid < 32) pref32[tid] = __popc(unionw[tid]);
    int* crow = &g_cand[row * KMAX];
    if (tid < KMAX) crow[tid] = -1;
    __syncthreads();
    if (tid == 0) {
        int acc = 0;
        for (int i = 0; i < 32; i++) { int t = pref32[i]; pref32[i] = acc; acc += t; }
    }
    __syncthreads();
    if (tid < 32) {
        unsigned m = unionw[tid];
        int rank = pref32[tid];
        while (m && rank < KMAX) {
            int bpos = __ffs(m) - 1;
            m &= m - 1;
            crow[rank] = tid * 32 + bpos;
            rank++;
        }
    }
}

// ---------------- K5: sparse attention over candidates ----------------------
// 1 warp per row; block 128 = 4 warps
__global__ void k_attn() {
    int wl = threadIdx.x >> 5;
    int lane = threadIdx.x & 31;
    int rid = blockIdx.x * 4 + wl;     // (b*H+h)*S + s
    __shared__ float sq[4][DKK];
    __shared__ int sj[4][KMAX];
    __shared__ float sp[4][KMAX];
    const float* qr = &g_qup[rid * DKK];
    sq[wl][lane] = qr[lane];
    sq[wl][lane + 32] = qr[lane + 32];
    const int* crow = &g_cand[rid * KMAX];
    sj[wl][lane] = crow[lane];
    sj[wl][lane + 32] = crow[lane + 32];
    __syncwarp();
    int base = (rid & ~(SS - 1)) * DKK;     // (b*H+h)*S*DK
    const float* kb = &g_kup[base];
    float l0 = NEGF, l1 = NEGF;
    int j0 = sj[wl][lane], j1 = sj[wl][lane + 32];
    if (j0 >= 0) {
        const float* kr = kb + j0 * DKK;
        float a = 0.f;
#pragma unroll
        for (int d = 0; d < DKK; d++) a += sq[wl][d] * kr[d];
        l0 = a * 0.125f;
    }
    if (j1 >= 0) {
        const float* kr = kb + j1 * DKK;
        float a = 0.f;
#pragma unroll
        for (int d = 0; d < DKK; d++) a += sq[wl][d] * kr[d];
        l1 = a * 0.125f;
    }
    float mx = fmaxf(l0, l1);
#pragma unroll
    for (int off = 16; off; off >>= 1) mx = fmaxf(mx, __shfl_xor_sync(0xffffffffu, mx, off));
    float e0 = (j0 >= 0) ? expf(l0 - mx) : 0.f;
    float e1 = (j1 >= 0) ? expf(l1 - mx) : 0.f;
    float ssum = e0 + e1;
#pragma unroll
    for (int off = 16; off; off >>= 1) ssum += __shfl_xor_sync(0xffffffffu, ssum, off);
    float inv = (ssum > 0.f) ? (1.f / ssum) : 0.f;
    sp[wl][lane] = e0 * inv;
    sp[wl][lane + 32] = e1 * inv;
    __syncwarp();
    const float* vb = &g_vup[base];
    float o0 = 0.f, o1 = 0.f;
    for (int c = 0; c < KMAX; c++) {
        int j = sj[wl][c];
        if (j < 0) break;
        float p = sp[wl][c];
        const float* vr = vb + j * DKK;
        o0 += p * vr[lane];
        o1 += p * vr[lane + 32];
    }
    g_outh[rid * DKK + lane] = o0;
    g_outh[rid * DKK + lane + 32] = o1;
}

// ---------------- K6: output projection out = out_h @ Wo --------------------
// grid (S/64, D/64, B), 256 threads
__global__ void k_out(const float* __restrict__ Wo, float* __restrict__ out) {
    int s0 = blockIdx.x * 64;
    int n0 = blockIdx.y * 64;
    int b = blockIdx.z;
    __shared__ float As[64][32];
    __shared__ float Bs[32][64];
    int tid = threadIdx.x;
    int tx = tid & 15, ty = tid >> 4;
    float c[4][4] = {};
    for (int c0 = 0; c0 < HH * DKK; c0 += 32) {
        int h = c0 >> 6;
        int kbase = c0 & 63;
        for (int i = tid; i < 64 * 32; i += 256) {
            int r = i >> 5, cc = i & 31;
            As[r][cc] = g_outh[(((b * HH + h) * SS) + s0 + r) * DKK + kbase + cc];
        }
        for (int i = tid; i < 32 * 64; i += 256) {
            int r = i >> 6, cc = i & 63;
            Bs[r][cc] = Wo[(c0 + r) * DD + n0 + cc];
        }
        __syncthreads();
#pragma unroll 8
        for (int d = 0; d < 32; d++) {
            float a0 = As[ty * 4 + 0][d];
            float a1 = As[ty * 4 + 1][d];
            float a2 = As[ty * 4 + 2][d];
            float a3 = As[ty * 4 + 3][d];
            float4 bv = *(const float4*)&Bs[d][tx * 4];
            c[0][0] += a0 * bv.x; c[0][1] += a0 * bv.y; c[0][2] += a0 * bv.z; c[0][3] += a0 * bv.w;
            c[1][0] += a1 * bv.x; c[1][1] += a1 * bv.y; c[1][2] += a1 * bv.z; c[1][3] += a1 * bv.w;
            c[2][0] += a2 * bv.x; c[2][1] += a2 * bv.y; c[2][2] += a2 * bv.z; c[2][3] += a2 * bv.w;
            c[3][0] += a3 * bv.x; c[3][1] += a3 * bv.y; c[3][2] += a3 * bv.z; c[3][3] += a3 * bv.w;
        }
        __syncthreads();
    }
    for (int i = 0; i < 4; i++) {
        int r = ty * 4 + i;
        float4 v = make_float4(c[i][0], c[i][1], c[i][2], c[i][3]);
        *(float4*)&out[(b * SS + s0 + r) * DD + n0 + tx * 4] = v;
    }
}

// ---------------- launch ----------------------------------------------------
extern "C" void kernel_launch(void* const* d_in, const int* in_sizes, int n_in,
                              void* d_out, int out_size) {
    const float* query = (const float*)d_in[0];
    const float* key   = (const float*)d_in[1];
    const float* value = (const float*)d_in[2];
    const float* Aq    = (const float*)d_in[3];
    const float* Bq    = (const float*)d_in[4];
    const float* Ak    = (const float*)d_in[5];
    const float* Bk    = (const float*)d_in[6];
    const float* Wv    = (const float*)d_in[7];
    const float* Wo    = (const float*)d_in[8];
    const float* lsh   = (const float*)d_in[9];
    float* out = (float*)d_out;

    k_projqk<<<BB * SS, 256>>>(query, key, Aq, Bq, Ak, Bk);
    k_vup<<<dim3(SS / 64, HH, BB), 256>>>(value, Wv);
    k_hash<<<(BB * HH * GG * SS + 255) / 256, 256>>>(lsh);
    k_cand<<<BB * HH * SS, 128>>>();
    k_attn<<<BB * HH * SS / 4, 128>>>();
    k_out<<<dim3(SS / 64, DD / 64, BB), 256>>>(Wo, out);
}

// round 2
// speedup vs baseline: 3.5000x; 3.5000x over previous
#include <cuda_runtime.h>
#include <cuda_bf16.h>
#include <stdint.h>

#define BB 2
#define SS 1024
#define DD 512
#define HH 8
#define DKK 64
#define RR 16
#define GG 2
#define GDD 32
#define NHH 4
#define KMAX 64
#define NEGF (-1e30f)

typedef unsigned long long ull;

// ---------------- scratch (device globals; no allocation allowed) ----------
__device__ float g_qup[BB*HH*SS*DKK];   // [b][h][s][k]
__device__ float g_kup[BB*HH*SS*DKK];
__device__ float g_vup[BB*HH*SS*DKK];
__device__ float g_outh[BB*HH*SS*DKK];
__device__ float g_tmpq[BB*SS*HH*RR];   // [bs][h*R+r]
__device__ float g_tmpk[BB*SS*HH*RR];
__device__ unsigned g_hq[BB*HH*GG*SS];  // packed 4 hash bytes
__device__ unsigned g_hk[BB*HH*GG*SS];
__device__ unsigned g_qsign[HH*GG*SS];  // sign masks from batch B-1
__device__ unsigned g_ksign[HH*GG*SS];
__device__ ull g_sorted[HH*GG][SS];     // (sign<<32)|idx, sorted
__device__ int g_cand[BB*HH*SS*KMAX];
__device__ int g_anyflag;
// overflow buffers for the (astronomically rare) many-match fallback path
__device__ int   g_midx[(size_t)BB*HH*SS*SS/ (SS/SS)]; // 16384*1024
__device__ float g_msc[(size_t)BB*HH*SS*1024];

__device__ __forceinline__ unsigned f2u_ord(float f) {
    unsigned u = __float_as_uint(f);
    return (u & 0x80000000u) ? ~u : (u | 0x80000000u);
}
__device__ __forceinline__ ull ffma2(ull a, ull b, ull c) {
    ull d;
    asm("fma.rn.f32x2 %0, %1, %2, %3;" : "=l"(d) : "l"(a), "l"(b), "l"(c));
    return d;
}
__device__ __forceinline__ ull packf2(float x, float y) {
    ull d;
    asm("mov.b64 %0, {%1, %2};" : "=l"(d) : "f"(x), "f"(y));
    return d;
}
__device__ __forceinline__ void unpackf2(ull v, float& lo, float& hi) {
    asm("mov.b64 {%0, %1}, %2;" : "=f"(lo), "=f"(hi) : "l"(v));
}

// ---------------- K1: stage-1 low-rank proj: tmp = X @ A  -------------------
// grid (2048/64, 128/64, 2{q,k}), 256 thr; 64x64 tile, K-chunks of 32, FFMA2
__global__ void k_proj1(const float* __restrict__ Xq, const float* __restrict__ Xk,
                        const float* __restrict__ Aq, const float* __restrict__ Ak) {
    int m0 = blockIdx.x * 64;
    int n0 = blockIdx.y * 64;
    int z = blockIdx.z;
    const float* X  = z ? Xk : Xq;
    const float* Am = z ? Ak : Aq;
    float* Tm = z ? g_tmpk : g_tmpq;
    __shared__ float As[32][66];   // As[d][row]
    __shared__ float Bs[32][68];   // Bs[d][col]
    int tid = threadIdx.x;
    int tx = tid & 15, ty = tid >> 4;
    ull acc[2][4] = {};            // row-pairs x 4 cols, packed f32x2
    for (int d0 = 0; d0 < DD; d0 += 32) {
#pragma unroll
        for (int t = 0; t < 2; t++) {
            int lin = tid + t * 256;
            int r = lin >> 3, d4 = lin & 7;
            float4 v = *(const float4*)&X[(m0 + r) * DD + d0 + d4 * 4];
            As[d4*4+0][r] = v.x; As[d4*4+1][r] = v.y;
            As[d4*4+2][r] = v.z; As[d4*4+3][r] = v.w;
        }
#pragma unroll
        for (int t = 0; t < 2; t++) {
            int lin = tid + t * 256;
            int r = lin >> 4;             // d-row 0..31
            int cc = (lin & 15) * 4;      // col 0..60
            int c = n0 + cc;
            int h = c >> 4, rr = c & 15;
            float4 v = *(const float4*)&Am[h * (DD * RR) + (d0 + r) * RR + rr];
            *(float4*)&Bs[r][cc] = v;
        }
        __syncthreads();
#pragma unroll
        for (int d = 0; d < 32; d++) {
            ull a01 = *(const ull*)&As[d][ty * 4];
            ull a23 = *(const ull*)&As[d][ty * 4 + 2];
            float4 bv = *(const float4*)&Bs[d][tx * 4];
            ull bx = packf2(bv.x, bv.x), by = packf2(bv.y, bv.y);
            ull bz2 = packf2(bv.z, bv.z), bw = packf2(bv.w, bv.w);
            acc[0][0] = ffma2(a01, bx, acc[0][0]);
            acc[0][1] = ffma2(a01, by, acc[0][1]);
            acc[0][2] = ffma2(a01, bz2, acc[0][2]);
            acc[0][3] = ffma2(a01, bw, acc[0][3]);
            acc[1][0] = ffma2(a23, bx, acc[1][0]);
            acc[1][1] = ffma2(a23, by, acc[1][1]);
            acc[1][2] = ffma2(a23, bz2, acc[1][2]);
            acc[1][3] = ffma2(a23, bw, acc[1][3]);
        }
        __syncthreads();
    }
#pragma unroll
    for (int pr = 0; pr < 2; pr++)
#pragma unroll
        for (int j = 0; j < 4; j++) {
            float lo, hi;
            unpackf2(acc[pr][j], lo, hi);
            Tm[(m0 + ty*4 + pr*2 + 0) * (HH*RR) + n0 + tx*4 + j] = lo;
            Tm[(m0 + ty*4 + pr*2 + 1) * (HH*RR) + n0 + tx*4 + j] = hi;
        }
}

// ---------------- K2: stage-2: qup/kup = tmp @ B per head -------------------
// grid (2048/64, H, 2), 256 thr
__global__ void k_proj2(const float* __restrict__ Bq, const float* __restrict__ Bk) {
    int m0 = blockIdx.x * 64;
    int h = blockIdx.y;
    int z = blockIdx.z;
    const float* Tm = z ? g_tmpk : g_tmpq;
    const float* Bm = (z ? Bk : Bq) + h * RR * DKK;
    float* Out = z ? g_kup : g_qup;
    __shared__ float As[64][17];
    __shared__ float Bs[16][68];
    int tid = threadIdx.x;
#pragma unroll
    for (int t = 0; t < 4; t++) {
        int lin = tid + t * 256;
        int r = lin >> 4, kk = lin & 15;
        As[r][kk] = Tm[(m0 + r) * (HH*RR) + h * RR + kk];
    }
#pragma unroll
    for (int t = 0; t < 4; t++) {
        int lin = tid + t * 256;
        int kk = lin >> 6, cc = lin & 63;
        Bs[kk][cc] = Bm[kk * DKK + cc];
    }
    __syncthreads();
    int tx = tid & 15, ty = tid >> 4;
    float c4[4][4] = {};
#pragma unroll
    for (int kk = 0; kk < 16; kk++) {
        float a0 = As[ty*4+0][kk], a1 = As[ty*4+1][kk];
        float a2 = As[ty*4+2][kk], a3 = As[ty*4+3][kk];
        float4 bv = *(const float4*)&Bs[kk][tx * 4];
        c4[0][0] += a0*bv.x; c4[0][1] += a0*bv.y; c4[0][2] += a0*bv.z; c4[0][3] += a0*bv.w;
        c4[1][0] += a1*bv.x; c4[1][1] += a1*bv.y; c4[1][2] += a1*bv.z; c4[1][3] += a1*bv.w;
        c4[2][0] += a2*bv.x; c4[2][1] += a2*bv.y; c4[2][2] += a2*bv.z; c4[2][3] += a2*bv.w;
        c4[3][0] += a3*bv.x; c4[3][1] += a3*bv.y; c4[3][2] += a3*bv.z; c4[3][3] += a3*bv.w;
    }
    int b = m0 >> 10;
    int sbase = m0 & (SS - 1);
#pragma unroll
    for (int i = 0; i < 4; i++) {
        int s = sbase + ty * 4 + i;
        float4 v = make_float4(c4[i][0], c4[i][1], c4[i][2], c4[i][3]);
        *(float4*)&Out[(((b * HH + h) * SS) + s) * DKK + tx * 4] = v;
    }
}

// ---------------- K3: LSH hashes + sign masks -------------------------------
__global__ void k_hash(const float* __restrict__ lsh) {
    int idx = blockIdx.x * 256 + threadIdx.x;
    if (idx == 0) g_anyflag = 0;
    if (idx >= BB * HH * GG * SS) return;
    int s = idx & (SS - 1);
    int g = (idx >> 10) & 1;
    int h = (idx >> 11) & 7;
    int b = idx >> 14;
    const float* qr = &g_qup[(((b * HH + h) * SS) + s) * DKK + g * GDD];
    const float* kr = &g_kup[(((b * HH + h) * SS) + s) * DKK + g * GDD];
    const float* pp = &lsh[(h * GG + g) * GDD * NHH];
    float pq[NHH] = {}, pk[NHH] = {};
    unsigned sq = 0u, sk = 0u;
#pragma unroll 8
    for (int d = 0; d < GDD; d++) {
        float qv = qr[d], kv = kr[d];
        if (qv > 0.f) sq |= (1u << d);
        if (kv > 0.f) sk |= (1u << d);
#pragma unroll
        for (int n = 0; n < NHH; n++) {
            float w = pp[d * NHH + n];
            pq[n] += qv * w;
            pk[n] += kv * w;
        }
    }
    unsigned hq = 0u, hk = 0u;
#pragma unroll
    for (int n = 0; n < NHH; n++) {
        int fq = (int)floorf(pq[n] * 0.25f);
        int fk = (int)floorf(pk[n] * 0.25f);
        hq |= ((unsigned)(fq & 63)) << (8 * n);
        hk |= ((unsigned)(fk & 63)) << (8 * n);
    }
    g_hq[idx] = hq;
    g_hk[idx] = hk;
    if (b == BB - 1) {
        g_qsign[(h * GG + g) * SS + s] = sq;
        g_ksign[(h * GG + g) * SS + s] = sk;
    }
}

// ---------------- K4: sort key sign masks per (h,g) -------------------------
__global__ void k_sortsign() {
    int hg = blockIdx.x;
    __shared__ ull arr[SS];
    int tid = threadIdx.x;  // 256
#pragma unroll
    for (int t = 0; t < 4; t++) {
        int i = tid + t * 256;
        arr[i] = (((ull)g_ksign[hg * SS + i]) << 32) | (unsigned)i;
    }
    __syncthreads();
    for (int k = 2; k <= SS; k <<= 1) {
        for (int j = k >> 1; j > 0; j >>= 1) {
            for (int t = 0; t < 4; t++) {
                int i = tid + t * 256;
                int ixj = i ^ j;
                if (ixj > i) {
                    ull a = arr[i], b2 = arr[ixj];
                    bool up = ((i & k) == 0);
                    if ((a > b2) == up) { arr[i] = b2; arr[ixj] = a; }
                }
            }
            __syncthreads();
        }
    }
#pragma unroll
    for (int t = 0; t < 4; t++) {
        int i = tid + t * 256;
        g_sorted[hg][i] = arr[i];
    }
}

// ---------------- K5: candidate generation (warp per row) -------------------
__global__ void k_cand() {
    __shared__ float qrow[4][DKK];
    __shared__ unsigned unionw[4][32];
    __shared__ unsigned gmask[4][32];
    int tid = threadIdx.x, wid = tid >> 5, lane = tid & 31;
    int row = blockIdx.x * 4 + wid;
    int s = row & (SS - 1), h = (row >> 10) & 7, b = row >> 13;
    qrow[wid][lane] = g_qup[row * DKK + lane];
    qrow[wid][lane + 32] = g_qup[row * DKK + lane + 32];
    unionw[wid][lane] = 0u;
    __syncwarp();
    int* mix = &g_midx[(size_t)row * 1024];
    float* msf = &g_msc[(size_t)row * 1024];
    for (int g = 0; g < GG; g++) {
        gmask[wid][lane] = 0u;
        __syncwarp();
        int hg = h * GG + g;
        unsigned qsig = g_qsign[hg * SS + s];
        unsigned hqv = g_hq[((b * HH + h) * GG + g) * SS + s];
        const ull* srt = g_sorted[hg];
        int l = 0;
        if (lane < 2) {
            bool skip = false;
            ull tgt = 0;
            if (lane == 0) tgt = ((ull)qsig) << 32;
            else {
                if (qsig == 0xFFFFFFFFu) { l = SS; skip = true; }
                else tgt = ((ull)(qsig + 1u)) << 32;
            }
            if (!skip) {
                int r2 = SS;
                while (l < r2) { int m = (l + r2) >> 1; if (srt[m] < tgt) l = m + 1; else r2 = m; }
            }
        }
        int lo = __shfl_sync(0xffffffffu, l, 0);
        int hi = __shfl_sync(0xffffffffu, l, 1);
        int gcnt = 0;
        const unsigned* hkp = &g_hk[((b * HH + h) * GG + g) * SS];
        const float* kbase = &g_kup[(b * HH + h) * SS * DKK + g * GDD];
        for (int p0 = lo; p0 < hi; p0 += 32) {
            int p = p0 + lane;
            bool mt = false; int j = 0;
            if (p < hi) {
                j = (int)(srt[p] & 0xffffffffu);
                mt = (__vcmpeq4(hqv, hkp[j]) != 0u);
            }
            unsigned bal = __ballot_sync(0xffffffffu, mt);
            if (mt) {
                int rk = gcnt + __popc(bal & ((1u << lane) - 1u));
                const float* kr = kbase + j * DKK;
                float a = 0.f;
#pragma unroll
                for (int d = 0; d < GDD; d++) a += qrow[wid][g * GDD + d] * kr[d];
                mix[rk] = j; msf[rk] = a;
                atomicOr(&gmask[wid][j >> 5], 1u << (j & 31));
            }
            gcnt += __popc(bal);
        }
        if (gcnt > KMAX) {
            // rare fallback: exact 64th-largest threshold via warp radix select
            gmask[wid][lane] = 0u;
            __syncwarp();
            unsigned prefix = 0u; int kk = KMAX;
            for (int bit = 31; bit >= 0; bit--) {
                int local = 0;
                for (int i = lane; i < gcnt; i += 32) {
                    unsigned key = f2u_ord(msf[i]);
                    unsigned hi2 = (bit == 31) ? 0u : (key >> (bit + 1));
                    if (hi2 == prefix && ((key >> bit) & 1u)) local++;
                }
#pragma unroll
                for (int off = 16; off; off >>= 1) local += __shfl_xor_sync(0xffffffffu, local, off);
                if (local >= kk) prefix = (prefix << 1) | 1u;
                else { kk -= local; prefix <<= 1; }
            }
            for (int i = lane; i < gcnt; i += 32)
                if (f2u_ord(msf[i]) >= prefix)
                    atomicOr(&gmask[wid][mix[i] >> 5], 1u << (mix[i] & 31));
        }
        __syncwarp();
        unionw[wid][lane] |= gmask[wid][lane];
        __syncwarp();
    }
    unsigned w = unionw[wid][lane];
    int c = __popc(w);
    int pre = c;
#pragma unroll
    for (int off = 1; off < 32; off <<= 1) {
        int n = __shfl_up_sync(0xffffffffu, pre, off);
        if (lane >= off) pre += n;
    }
    int excl = pre - c;
    int total = __shfl_sync(0xffffffffu, pre, 31);
    int* crow = &g_cand[row * KMAX];
    crow[lane] = -1; crow[lane + 32] = -1;
    __syncwarp();
    int rank = excl;
    while (w && rank < KMAX) {
        int bpos = __ffs(w) - 1;
        w &= w - 1;
        crow[rank++] = lane * 32 + bpos;
    }
    if (lane == 0 && total > 0) atomicAdd(&g_anyflag, 1);
}

// ---------------- K6: v_up = value @ Wv (guarded fallback) ------------------
__global__ void k_vup(const float* __restrict__ value, const float* __restrict__ Wv) {
    if (g_anyflag == 0) return;  // vup only consumed via candidates
    int s0 = blockIdx.x * 64;
    int h = blockIdx.y, b = blockIdx.z;
    __shared__ float As[64][32];
    __shared__ float Bs[32][64];
    int tid = threadIdx.x;
    int tx = tid & 15, ty = tid >> 4;
    float c[4][4] = {};
    for (int d0 = 0; d0 < DD; d0 += 32) {
        for (int i = tid; i < 64 * 32; i += 256) {
            int r = i >> 5, cc = i & 31;
            As[r][cc] = value[(b * SS + s0 + r) * DD + d0 + cc];
        }
        for (int i = tid; i < 32 * 64; i += 256) {
            int r = i >> 6, cc = i & 63;
            Bs[r][cc] = Wv[h * DD * DKK + (d0 + r) * DKK + cc];
        }
        __syncthreads();
#pragma unroll 8
        for (int d = 0; d < 32; d++) {
            float a0 = As[ty*4+0][d], a1 = As[ty*4+1][d];
            float a2 = As[ty*4+2][d], a3 = As[ty*4+3][d];
            float4 bv = *(const float4*)&Bs[d][tx * 4];
            c[0][0] += a0*bv.x; c[0][1] += a0*bv.y; c[0][2] += a0*bv.z; c[0][3] += a0*bv.w;
            c[1][0] += a1*bv.x; c[1][1] += a1*bv.y; c[1][2] += a1*bv.z; c[1][3] += a1*bv.w;
            c[2][0] += a2*bv.x; c[2][1] += a2*bv.y; c[2][2] += a2*bv.z; c[2][3] += a2*bv.w;
            c[3][0] += a3*bv.x; c[3][1] += a3*bv.y; c[3][2] += a3*bv.z; c[3][3] += a3*bv.w;
        }
        __syncthreads();
    }
    for (int i = 0; i < 4; i++) {
        int r = ty * 4 + i;
        float4 v = make_float4(c[i][0], c[i][1], c[i][2], c[i][3]);
        *(float4*)&g_vup[(((b * HH + h) * SS) + s0 + r) * DKK + tx * 4] = v;
    }
}

// ---------------- K7: sparse attention over candidates ----------------------
__global__ void k_attn() {
    if (g_anyflag == 0) return;  // outh unused when no candidates anywhere
    int wl = threadIdx.x >> 5;
    int lane = threadIdx.x & 31;
    int rid = blockIdx.x * 4 + wl;
    __shared__ float sq[4][DKK];
    __shared__ int sj[4][KMAX];
    __shared__ float sp[4][KMAX];
    const float* qr = &g_qup[rid * DKK];
    sq[wl][lane] = qr[lane];
    sq[wl][lane + 32] = qr[lane + 32];
    const int* crow = &g_cand[rid * KMAX];
    sj[wl][lane] = crow[lane];
    sj[wl][lane + 32] = crow[lane + 32];
    __syncwarp();
    int base = (rid & ~(SS - 1)) * DKK;
    const float* kb = &g_kup[base];
    float l0 = NEGF, l1 = NEGF;
    int j0 = sj[wl][lane], j1 = sj[wl][lane + 32];
    if (j0 >= 0) {
        const float* kr = kb + j0 * DKK;
        float a = 0.f;
#pragma unroll
        for (int d = 0; d < DKK; d++) a += sq[wl][d] * kr[d];
        l0 = a * 0.125f;
    }
    if (j1 >= 0) {
        const float* kr = kb + j1 * DKK;
        float a = 0.f;
#pragma unroll
        for (int d = 0; d < DKK; d++) a += sq[wl][d] * kr[d];
        l1 = a * 0.125f;
    }
    float mx = fmaxf(l0, l1);
#pragma unroll
    for (int off = 16; off; off >>= 1) mx = fmaxf(mx, __shfl_xor_sync(0xffffffffu, mx, off));
    float e0 = (j0 >= 0) ? expf(l0 - mx) : 0.f;
    float e1 = (j1 >= 0) ? expf(l1 - mx) : 0.f;
    float ssum = e0 + e1;
#pragma unroll
    for (int off = 16; off; off >>= 1) ssum += __shfl_xor_sync(0xffffffffu, ssum, off);
    float inv = (ssum > 0.f) ? (1.f / ssum) : 0.f;
    sp[wl][lane] = e0 * inv;
    sp[wl][lane + 32] = e1 * inv;
    __syncwarp();
    const float* vb = &g_vup[base];
    float o0 = 0.f, o1 = 0.f;
    for (int c = 0; c < KMAX; c++) {
        int j = sj[wl][c];
        if (j < 0) break;
        float p = sp[wl][c];
        const float* vr = vb + j * DKK;
        o0 += p * vr[lane];
        o1 += p * vr[lane + 32];
    }
    g_outh[rid * DKK + lane] = o0;
    g_outh[rid * DKK + lane + 32] = o1;
}

// ---------------- K8: output projection (guarded zero-fill) -----------------
__global__ void k_out(const float* __restrict__ Wo, float* __restrict__ out) {
    int s0 = blockIdx.x * 64;
    int n0 = blockIdx.y * 64;
    int b = blockIdx.z;
    int tid = threadIdx.x;
    int tx = tid & 15, ty = tid >> 4;
    if (g_anyflag == 0) {
        float4 z = make_float4(0.f, 0.f, 0.f, 0.f);
#pragma unroll
        for (int i = 0; i < 4; i++) {
            int r = ty * 4 + i;
            *(float4*)&out[(b * SS + s0 + r) * DD + n0 + tx * 4] = z;
        }
        return;
    }
    __shared__ float As[64][32];
    __shared__ float Bs[32][64];
    float c[4][4] = {};
    for (int c0 = 0; c0 < HH * DKK; c0 += 32) {
        int h = c0 >> 6;
        int kbase = c0 & 63;
        for (int i = tid; i < 64 * 32; i += 256) {
            int r = i >> 5, cc = i & 31;
            As[r][cc] = g_outh[(((b * HH + h) * SS) + s0 + r) * DKK + kbase + cc];
        }
        for (int i = tid; i < 32 * 64; i += 256) {
            int r = i >> 6, cc = i & 63;
            Bs[r][cc] = Wo[(c0 + r) * DD + n0 + cc];
        }
        __syncthreads();
#pragma unroll 8
        for (int d = 0; d < 32; d++) {
            float a0 = As[ty*4+0][d], a1 = As[ty*4+1][d];
            float a2 = As[ty*4+2][d], a3 = As[ty*4+3][d];
            float4 bv = *(const float4*)&Bs[d][tx * 4];
            c[0][0] += a0*bv.x; c[0][1] += a0*bv.y; c[0][2] += a0*bv.z; c[0][3] += a0*bv.w;
            c[1][0] += a1*bv.x; c[1][1] += a1*bv.y; c[1][2] += a1*bv.z; c[1][3] += a1*bv.w;
            c[2][0] += a2*bv.x; c[2][1] += a2*bv.y; c[2][2] += a2*bv.z; c[2][3] += a2*bv.w;
            c[3][0] += a3*bv.x; c[3][1] += a3*bv.y; c[3][2] += a3*bv.z; c[3][3] += a3*bv.w;
        }
        __syncthreads();
    }
    for (int i = 0; i < 4; i++) {
        int r = ty * 4 + i;
        float4 v = make_float4(c[i][0], c[i][1], c[i][2], c[i][3]);
        *(float4*)&out[(b * SS + s0 + r) * DD + n0 + tx * 4] = v;
    }
}

// ---------------- launch ----------------------------------------------------
extern "C" void kernel_launch(void* const* d_in, const int* in_sizes, int n_in,
                              void* d_out, int out_size) {
    const float* query = (const float*)d_in[0];
    const float* key   = (const float*)d_in[1];
    const float* value = (const float*)d_in[2];
    const float* Aq    = (const float*)d_in[3];
    const float* Bq    = (const float*)d_in[4];
    const float* Ak    = (const float*)d_in[5];
    const float* Bk    = (const float*)d_in[6];
    const float* Wv    = (const float*)d_in[7];
    const float* Wo    = (const float*)d_in[8];
    const float* lsh   = (const float*)d_in[9];
    float* out = (float*)d_out;

    k_proj1<<<dim3(BB * SS / 64, (HH * RR) / 64, 2), 256>>>(query, key, Aq, Ak);
    k_proj2<<<dim3(BB * SS / 64, HH, 2), 256>>>(Bq, Bk);
    k_hash<<<(BB * HH * GG * SS + 255) / 256, 256>>>(lsh);
    k_sortsign<<<HH * GG, 256>>>();
    k_cand<<<BB * HH * SS / 4, 128>>>();
    k_vup<<<dim3(SS / 64, HH, BB), 256>>>(value, Wv);
    k_attn<<<BB * HH * SS / 4, 128>>>();
    k_out<<<dim3(SS / 64, DD / 64, BB), 256>>>(Wo, out);
}

// round 3
// speedup vs baseline: 4.4195x; 1.2627x over previous
#include <cuda_runtime.h>
#include <cuda_bf16.h>
#include <stdint.h>

#define BB 2
#define SS 1024
#define DD 512
#define HH 8
#define DKK 64
#define RR 16
#define GG 2
#define GDD 32
#define NHH 4
#define KMAX 64
#define NEGF (-1e30f)
#define TSLOTS 2048

typedef unsigned long long ull;

// ---------------- scratch (device globals; no allocation allowed) ----------
__device__ float g_qup[BB*HH*SS*DKK];   // [b][h][s][k]
__device__ float g_kup[BB*HH*SS*DKK];
__device__ float g_vup[BB*HH*SS*DKK];
__device__ float g_outh[BB*HH*SS*DKK];
__device__ unsigned g_hq[BB*HH*GG*SS];  // packed 4 hash bytes
__device__ unsigned g_hk[BB*HH*GG*SS];
__device__ unsigned g_qsign[HH*GG*SS];  // q sign masks from batch B-1
__device__ ull g_htab[HH*GG][TSLOTS];   // (ksign<<32)|idx, linear probing
__device__ int g_cand[BB*HH*SS*KMAX];
__device__ int g_anyflag;
// overflow buffers for the (astronomically rare) many-match fallback path
__device__ int   g_midx[(size_t)BB*HH*SS*1024];
__device__ float g_msc[(size_t)BB*HH*SS*1024];

__device__ __forceinline__ unsigned f2u_ord(float f) {
    unsigned u = __float_as_uint(f);
    return (u & 0x80000000u) ? ~u : (u | 0x80000000u);
}
__device__ __forceinline__ ull ffma2(ull a, ull b, ull c) {
    ull d;
    asm("fma.rn.f32x2 %0, %1, %2, %3;" : "=l"(d) : "l"(a), "l"(b), "l"(c));
    return d;
}
__device__ __forceinline__ ull packf2(float x, float y) {
    ull d;
    asm("mov.b64 %0, {%1, %2};" : "=l"(d) : "f"(x), "f"(y));
    return d;
}
__device__ __forceinline__ void unpackf2(ull v, float& lo, float& hi) {
    asm("mov.b64 {%0, %1}, %2;" : "=f"(lo), "=f"(hi) : "l"(v));
}

// ---------------- K0: clear hash tables + flag -------------------------------
__global__ void k_init() {
    int i = blockIdx.x * 256 + threadIdx.x;
    ((ull*)g_htab)[i] = ~0ull;
    if (i == 0) g_anyflag = 0;
}

// ---------------- K1: fused low-rank projection ------------------------------
// stage1: tmp_tile[64 rows][64 cols] = X_tile @ A_tile (K=512)   (kept in smem)
// stage2: for each of the 4 heads covered by the 64 tmp cols:
//         out_tile[64 rows][64 dk] = tmp_h[64x16] @ B_h[16x64]
// grid (2048/64, 128/64, 2{q,k}), 256 thr
__global__ void k_proj(const float* __restrict__ Xq, const float* __restrict__ Xk,
                       const float* __restrict__ Aq, const float* __restrict__ Ak,
                       const float* __restrict__ Bq, const float* __restrict__ Bk) {
    int m0 = blockIdx.x * 64;
    int n0 = blockIdx.y * 64;
    int z = blockIdx.z;
    const float* X  = z ? Xk : Xq;
    const float* Am = z ? Ak : Aq;
    const float* Bm = z ? Bk : Bq;
    float* Out = z ? g_kup : g_qup;
    __shared__ float As[32][66];   // stage1: As[d][row]
    __shared__ float Bs[32][68];   // stage1 B / stage2 B_h (16x68 used)
    __shared__ float Ts[64][68];   // stage1 result tile
    int tid = threadIdx.x;
    int tx = tid & 15, ty = tid >> 4;
    ull acc[2][4] = {};            // row-pairs x 4 cols, packed f32x2
    for (int d0 = 0; d0 < DD; d0 += 32) {
#pragma unroll
        for (int t = 0; t < 2; t++) {
            int lin = tid + t * 256;
            int r = lin >> 3, d4 = lin & 7;
            float4 v = *(const float4*)&X[(m0 + r) * DD + d0 + d4 * 4];
            As[d4*4+0][r] = v.x; As[d4*4+1][r] = v.y;
            As[d4*4+2][r] = v.z; As[d4*4+3][r] = v.w;
        }
#pragma unroll
        for (int t = 0; t < 2; t++) {
            int lin = tid + t * 256;
            int r = lin >> 4;             // d-row 0..31
            int cc = (lin & 15) * 4;      // col 0..60
            int c = n0 + cc;
            int h = c >> 4, rr = c & 15;
            float4 v = *(const float4*)&Am[h * (DD * RR) + (d0 + r) * RR + rr];
            *(float4*)&Bs[r][cc] = v;
        }
        __syncthreads();
#pragma unroll
        for (int d = 0; d < 32; d++) {
            ull a01 = *(const ull*)&As[d][ty * 4];
            ull a23 = *(const ull*)&As[d][ty * 4 + 2];
            float4 bv = *(const float4*)&Bs[d][tx * 4];
            ull bx = packf2(bv.x, bv.x), by = packf2(bv.y, bv.y);
            ull bz2 = packf2(bv.z, bv.z), bw = packf2(bv.w, bv.w);
            acc[0][0] = ffma2(a01, bx, acc[0][0]);
            acc[0][1] = ffma2(a01, by, acc[0][1]);
            acc[0][2] = ffma2(a01, bz2, acc[0][2]);
            acc[0][3] = ffma2(a01, bw, acc[0][3]);
            acc[1][0] = ffma2(a23, bx, acc[1][0]);
            acc[1][1] = ffma2(a23, by, acc[1][1]);
            acc[1][2] = ffma2(a23, bz2, acc[1][2]);
            acc[1][3] = ffma2(a23, bw, acc[1][3]);
        }
        __syncthreads();
    }
    // stage1 result -> smem
#pragma unroll
    for (int pr = 0; pr < 2; pr++)
#pragma unroll
        for (int j = 0; j < 4; j++) {
            float lo, hi;
            unpackf2(acc[pr][j], lo, hi);
            Ts[ty*4 + pr*2 + 0][tx*4 + j] = lo;
            Ts[ty*4 + pr*2 + 1][tx*4 + j] = hi;
        }
    __syncthreads();
    // stage2: per-head K=16 GEMM from smem
    int b = m0 >> 10;
    int sbase = m0 & (SS - 1);
    int h0 = n0 >> 4;                  // first of 4 heads covered
#pragma unroll
    for (int hl = 0; hl < 4; hl++) {
        int h = h0 + hl;
        // load B_h[16][64]
#pragma unroll
        for (int t = 0; t < 4; t++) {
            int lin = tid + t * 256;
            int kk = lin >> 6, cc = lin & 63;
            Bs[kk][cc] = Bm[h * RR * DKK + kk * DKK + cc];
        }
        __syncthreads();
        float c4[4][4] = {};
#pragma unroll
        for (int kk = 0; kk < 16; kk++) {
            float a0 = Ts[ty*4+0][hl*16+kk], a1 = Ts[ty*4+1][hl*16+kk];
            float a2 = Ts[ty*4+2][hl*16+kk], a3 = Ts[ty*4+3][hl*16+kk];
            float4 bv = *(const float4*)&Bs[kk][tx * 4];
            c4[0][0] += a0*bv.x; c4[0][1] += a0*bv.y; c4[0][2] += a0*bv.z; c4[0][3] += a0*bv.w;
            c4[1][0] += a1*bv.x; c4[1][1] += a1*bv.y; c4[1][2] += a1*bv.z; c4[1][3] += a1*bv.w;
            c4[2][0] += a2*bv.x; c4[2][1] += a2*bv.y; c4[2][2] += a2*bv.z; c4[2][3] += a2*bv.w;
            c4[3][0] += a3*bv.x; c4[3][1] += a3*bv.y; c4[3][2] += a3*bv.z; c4[3][3] += a3*bv.w;
        }
#pragma unroll
        for (int i = 0; i < 4; i++) {
            int s = sbase + ty * 4 + i;
            float4 v = make_float4(c4[i][0], c4[i][1], c4[i][2], c4[i][3]);
            *(float4*)&Out[(((b * HH + h) * SS) + s) * DKK + tx * 4] = v;
        }
        __syncthreads();
    }
}

// ---------------- K2: LSH hashes + sign masks + hash-table build ------------
__global__ void k_hash(const float* __restrict__ lsh) {
    int idx = blockIdx.x * 256 + threadIdx.x;
    if (idx >= BB * HH * GG * SS) return;
    int s = idx & (SS - 1);
    int g = (idx >> 10) & 1;
    int h = (idx >> 11) & 7;
    int b = idx >> 14;
    const float* qr = &g_qup[(((b * HH + h) * SS) + s) * DKK + g * GDD];
    const float* kr = &g_kup[(((b * HH + h) * SS) + s) * DKK + g * GDD];
    const float* pp = &lsh[(h * GG + g) * GDD * NHH];
    float pq[NHH] = {}, pk[NHH] = {};
    unsigned sq = 0u, sk = 0u;
#pragma unroll 8
    for (int d = 0; d < GDD; d++) {
        float qv = qr[d], kv = kr[d];
        if (qv > 0.f) sq |= (1u << d);
        if (kv > 0.f) sk |= (1u << d);
#pragma unroll
        for (int n = 0; n < NHH; n++) {
            float w = pp[d * NHH + n];
            pq[n] += qv * w;
            pk[n] += kv * w;
        }
    }
    unsigned hq = 0u, hk = 0u;
#pragma unroll
    for (int n = 0; n < NHH; n++) {
        int fq = (int)floorf(pq[n] * 0.25f);
        int fk = (int)floorf(pk[n] * 0.25f);
        hq |= ((unsigned)(fq & 63)) << (8 * n);
        hk |= ((unsigned)(fk & 63)) << (8 * n);
    }
    g_hq[idx] = hq;
    g_hk[idx] = hk;
    if (b == BB - 1) {
        int hg = h * GG + g;
        g_qsign[hg * SS + s] = sq;
        // insert key sign into linear-probing table
        ull entry = (((ull)sk) << 32) | (unsigned)s;
        unsigned slot = (sk * 2654435761u) >> 21;   // 11 bits
        while (atomicCAS(&g_htab[hg][slot & (TSLOTS-1)], ~0ull, entry) != ~0ull)
            slot++;
    }
}

// ---------------- K3: candidate generation (warp per row) -------------------
__global__ void k_cand() {
    __shared__ float qrow[4][DKK];
    __shared__ unsigned unionw[4][32];
    __shared__ unsigned gmask[4][32];
    int tid = threadIdx.x, wid = tid >> 5, lane = tid & 31;
    int row = blockIdx.x * 4 + wid;
    int s = row & (SS - 1), h = (row >> 10) & 7, b = row >> 13;
    qrow[wid][lane] = g_qup[row * DKK + lane];
    qrow[wid][lane + 32] = g_qup[row * DKK + lane + 32];
    unionw[wid][lane] = 0u;
    __syncwarp();
    int* mix = &g_midx[(size_t)row * 1024];
    float* msf = &g_msc[(size_t)row * 1024];
    for (int g = 0; g < GG; g++) {
        gmask[wid][lane] = 0u;
        __syncwarp();
        int hg = h * GG + g;
        unsigned qsig = g_qsign[hg * SS + s];
        unsigned hqv = g_hq[((b * HH + h) * GG + g) * SS + s];
        const ull* tab = g_htab[hg];
        const unsigned* hkp = &g_hk[((b * HH + h) * GG + g) * SS];
        const float* kbase = &g_kup[(b * HH + h) * SS * DKK + g * GDD];
        unsigned start = (qsig * 2654435761u) >> 21;
        int gcnt = 0;
        for (int w = 0; w < TSLOTS / 32; w++) {
            int p = (start + w * 32 + lane) & (TSLOTS - 1);
            ull e = tab[p];
            bool empty = (e == ~0ull);
            unsigned em = __ballot_sync(0xffffffffu, empty);
            unsigned valid = em ? ((em & (unsigned)(-(int)em)) - 1u) : 0xffffffffu;
            bool mt = false; int j = 0;
            if (!empty && ((valid >> lane) & 1u) && (unsigned)(e >> 32) == qsig) {
                j = (int)(e & 0xffffffffu);
                mt = (__vcmpeq4(hqv, hkp[j]) != 0u);
            }
            unsigned bal = __ballot_sync(0xffffffffu, mt);
            if (mt) {
                int rk = gcnt + __popc(bal & ((1u << lane) - 1u));
                const float* kr = kbase + j * DKK;
                float a = 0.f;
#pragma unroll
                for (int d = 0; d < GDD; d++) a += qrow[wid][g * GDD + d] * kr[d];
                mix[rk] = j; msf[rk] = a;
                atomicOr(&gmask[wid][j >> 5], 1u << (j & 31));
            }
            gcnt += __popc(bal);
            if (em) break;
        }
        if (gcnt > KMAX) {
            // rare fallback: exact 64th-largest threshold via warp radix select
            gmask[wid][lane] = 0u;
            __syncwarp();
            unsigned prefix = 0u; int kk = KMAX;
            for (int bit = 31; bit >= 0; bit--) {
                int local = 0;
                for (int i = lane; i < gcnt; i += 32) {
                    unsigned key = f2u_ord(msf[i]);
                    unsigned hi2 = (bit == 31) ? 0u : (key >> (bit + 1));
                    if (hi2 == prefix && ((key >> bit) & 1u)) local++;
                }
#pragma unroll
                for (int off = 16; off; off >>= 1) local += __shfl_xor_sync(0xffffffffu, local, off);
                if (local >= kk) prefix = (prefix << 1) | 1u;
                else { kk -= local; prefix <<= 1; }
            }
            for (int i = lane; i < gcnt; i += 32)
                if (f2u_ord(msf[i]) >= prefix)
                    atomicOr(&gmask[wid][mix[i] >> 5], 1u << (mix[i] & 31));
        }
        __syncwarp();
        unionw[wid][lane] |= gmask[wid][lane];
        __syncwarp();
    }
    unsigned w = unionw[wid][lane];
    int c = __popc(w);
    int pre = c;
#pragma unroll
    for (int off = 1; off < 32; off <<= 1) {
        int n = __shfl_up_sync(0xffffffffu, pre, off);
        if (lane >= off) pre += n;
    }
    int excl = pre - c;
    int total = __shfl_sync(0xffffffffu, pre, 31);
    int* crow = &g_cand[row * KMAX];
    crow[lane] = -1; crow[lane + 32] = -1;
    __syncwarp();
    int rank = excl;
    while (w && rank < KMAX) {
        int bpos = __ffs(w) - 1;
        w &= w - 1;
        crow[rank++] = lane * 32 + bpos;
    }
    if (lane == 0 && total > 0) atomicAdd(&g_anyflag, 1);
}

// ---------------- K4: v_up = value @ Wv (guarded fallback) ------------------
__global__ void k_vup(const float* __restrict__ value, const float* __restrict__ Wv) {
    if (g_anyflag == 0) return;  // vup only consumed via candidates
    int s0 = blockIdx.x * 64;
    int h = blockIdx.y, b = blockIdx.z;
    __shared__ float As[64][32];
    __shared__ float Bs[32][64];
    int tid = threadIdx.x;
    int tx = tid & 15, ty = tid >> 4;
    float c[4][4] = {};
    for (int d0 = 0; d0 < DD; d0 += 32) {
        for (int i = tid; i < 64 * 32; i += 256) {
            int r = i >> 5, cc = i & 31;
            As[r][cc] = value[(b * SS + s0 + r) * DD + d0 + cc];
        }
        for (int i = tid; i < 32 * 64; i += 256) {
            int r = i >> 6, cc = i & 63;
            Bs[r][cc] = Wv[h * DD * DKK + (d0 + r) * DKK + cc];
        }
        __syncthreads();
#pragma unroll 8
        for (int d = 0; d < 32; d++) {
            float a0 = As[ty*4+0][d], a1 = As[ty*4+1][d];
            float a2 = As[ty*4+2][d], a3 = As[ty*4+3][d];
            float4 bv = *(const float4*)&Bs[d][tx * 4];
            c[0][0] += a0*bv.x; c[0][1] += a0*bv.y; c[0][2] += a0*bv.z; c[0][3] += a0*bv.w;
            c[1][0] += a1*bv.x; c[1][1] += a1*bv.y; c[1][2] += a1*bv.z; c[1][3] += a1*bv.w;
            c[2][0] += a2*bv.x; c[2][1] += a2*bv.y; c[2][2] += a2*bv.z; c[2][3] += a2*bv.w;
            c[3][0] += a3*bv.x; c[3][1] += a3*bv.y; c[3][2] += a3*bv.z; c[3][3] += a3*bv.w;
        }
        __syncthreads();
    }
    for (int i = 0; i < 4; i++) {
        int r = ty * 4 + i;
        float4 v = make_float4(c[i][0], c[i][1], c[i][2], c[i][3]);
        *(float4*)&g_vup[(((b * HH + h) * SS) + s0 + r) * DKK + tx * 4] = v;
    }
}

// ---------------- K5: sparse attention over candidates ----------------------
__global__ void k_attn() {
    if (g_anyflag == 0) return;  // outh unused when no candidates anywhere
    int wl = threadIdx.x >> 5;
    int lane = threadIdx.x & 31;
    int rid = blockIdx.x * 4 + wl;
    __shared__ float sq[4][DKK];
    __shared__ int sj[4][KMAX];
    __shared__ float sp[4][KMAX];
    const float* qr = &g_qup[rid * DKK];
    sq[wl][lane] = qr[lane];
    sq[wl][lane + 32] = qr[lane + 32];
    const int* crow = &g_cand[rid * KMAX];
    sj[wl][lane] = crow[lane];
    sj[wl][lane + 32] = crow[lane + 32];
    __syncwarp();
    int base = (rid & ~(SS - 1)) * DKK;
    const float* kb = &g_kup[base];
    float l0 = NEGF, l1 = NEGF;
    int j0 = sj[wl][lane], j1 = sj[wl][lane + 32];
    if (j0 >= 0) {
        const float* kr = kb + j0 * DKK;
        float a = 0.f;
#pragma unroll
        for (int d = 0; d < DKK; d++) a += sq[wl][d] * kr[d];
        l0 = a * 0.125f;
    }
    if (j1 >= 0) {
        const float* kr = kb + j1 * DKK;
        float a = 0.f;
#pragma unroll
        for (int d = 0; d < DKK; d++) a += sq[wl][d] * kr[d];
        l1 = a * 0.125f;
    }
    float mx = fmaxf(l0, l1);
#pragma unroll
    for (int off = 16; off; off >>= 1) mx = fmaxf(mx, __shfl_xor_sync(0xffffffffu, mx, off));
    float e0 = (j0 >= 0) ? expf(l0 - mx) : 0.f;
    float e1 = (j1 >= 0) ? expf(l1 - mx) : 0.f;
    float ssum = e0 + e1;
#pragma unroll
    for (int off = 16; off; off >>= 1) ssum += __shfl_xor_sync(0xffffffffu, ssum, off);
    float inv = (ssum > 0.f) ? (1.f / ssum) : 0.f;
    sp[wl][lane] = e0 * inv;
    sp[wl][lane + 32] = e1 * inv;
    __syncwarp();
    const float* vb = &g_vup[base];
    float o0 = 0.f, o1 = 0.f;
    for (int c = 0; c < KMAX; c++) {
        int j = sj[wl][c];
        if (j < 0) break;
        float p = sp[wl][c];
        const float* vr = vb + j * DKK;
        o0 += p * vr[lane];
        o1 += p * vr[lane + 32];
    }
    g_outh[rid * DKK + lane] = o0;
    g_outh[rid * DKK + lane + 32] = o1;
}

// ---------------- K6: output projection (guarded zero-fill) -----------------
__global__ void k_out(const float* __restrict__ Wo, float* __restrict__ out) {
    int s0 = blockIdx.x * 64;
    int n0 = blockIdx.y * 64;
    int b = blockIdx.z;
    int tid = threadIdx.x;
    int tx = tid & 15, ty = tid >> 4;
    if (g_anyflag == 0) {
        float4 z = make_float4(0.f, 0.f, 0.f, 0.f);
#pragma unroll
        for (int i = 0; i < 4; i++) {
            int r = ty * 4 + i;
            *(float4*)&out[(b * SS + s0 + r) * DD + n0 + tx * 4] = z;
        }
        return;
    }
    __shared__ float As[64][32];
    __shared__ float Bs[32][64];
    float c[4][4] = {};
    for (int c0 = 0; c0 < HH * DKK; c0 += 32) {
        int h = c0 >> 6;
        int kbase = c0 & 63;
        for (int i = tid; i < 64 * 32; i += 256) {
            int r = i >> 5, cc = i & 31;
            As[r][cc] = g_outh[(((b * HH + h) * SS) + s0 + r) * DKK + kbase + cc];
        }
        for (int i = tid; i < 32 * 64; i += 256) {
            int r = i >> 6, cc = i & 63;
            Bs[r][cc] = Wo[(c0 + r) * DD + n0 + cc];
        }
        __syncthreads();
#pragma unroll 8
        for (int d = 0; d < 32; d++) {
            float a0 = As[ty*4+0][d], a1 = As[ty*4+1][d];
            float a2 = As[ty*4+2][d], a3 = As[ty*4+3][d];
            float4 bv = *(const float4*)&Bs[d][tx * 4];
            c[0][0] += a0*bv.x; c[0][1] += a0*bv.y; c[0][2] += a0*bv.z; c[0][3] += a0*bv.w;
            c[1][0] += a1*bv.x; c[1][1] += a1*bv.y; c[1][2] += a1*bv.z; c[1][3] += a1*bv.w;
            c[2][0] += a2*bv.x; c[2][1] += a2*bv.y; c[2][2] += a2*bv.z; c[2][3] += a2*bv.w;
            c[3][0] += a3*bv.x; c[3][1] += a3*bv.y; c[3][2] += a3*bv.z; c[3][3] += a3*bv.w;
        }
        __syncthreads();
    }
    for (int i = 0; i < 4; i++) {
        int r = ty * 4 + i;
        float4 v = make_float4(c[i][0], c[i][1], c[i][2], c[i][3]);
        *(float4*)&out[(b * SS + s0 + r) * DD + n0 + tx * 4] = v;
    }
}

// ---------------- launch ----------------------------------------------------
extern "C" void kernel_launch(void* const* d_in, const int* in_sizes, int n_in,
                              void* d_out, int out_size) {
    const float* query = (const float*)d_in[0];
    const float* key   = (const float*)d_in[1];
    const float* value = (const float*)d_in[2];
    const float* Aq    = (const float*)d_in[3];
    const float* Bq    = (const float*)d_in[4];
    const float* Ak    = (const float*)d_in[5];
    const float* Bk    = (const float*)d_in[6];
    const float* Wv    = (const float*)d_in[7];
    const float* Wo    = (const float*)d_in[8];
    const float* lsh   = (const float*)d_in[9];
    float* out = (float*)d_out;

    k_init<<<(HH * GG * TSLOTS) / 256, 256>>>();
    k_proj<<<dim3(BB * SS / 64, (HH * RR) / 64, 2), 256>>>(query, key, Aq, Ak, Bq, Bk);
    k_hash<<<(BB * HH * GG * SS + 255) / 256, 256>>>(lsh);
    k_cand<<<BB * HH * SS / 4, 128>>>();
    k_vup<<<dim3(SS / 64, HH, BB), 256>>>(value, Wv);
    k_attn<<<BB * HH * SS / 4, 128>>>();
    k_out<<<dim3(SS / 64, DD / 64, BB), 256>>>(Wo, out);
}

// round 4
// speedup vs baseline: 4.4310x; 1.0026x over previous
#include <cuda_runtime.h>
#include <cuda_bf16.h>
#include <stdint.h>

#define BB 2
#define SS 1024
#define DD 512
#define HH 8
#define DKK 64
#define RR 16
#define GG 2
#define GDD 32
#define NHH 4
#define KMAX 64
#define NEGF (-1e30f)
#define TSLOTS 2048

typedef unsigned long long ull;

// ---------------- scratch (device globals; no allocation allowed) ----------
__device__ float g_qup[BB*HH*SS*DKK];   // [b][h][s][k]
__device__ float g_kup[BB*HH*SS*DKK];
__device__ float g_vup[BB*HH*SS*DKK];
__device__ float g_outh[BB*HH*SS*DKK];
__device__ unsigned g_hq[BB*HH*GG*SS];  // packed 4 hash bytes
__device__ unsigned g_hk[BB*HH*GG*SS];
__device__ unsigned g_qsign[HH*GG*SS];  // q sign masks from batch B-1
__device__ ull g_htab[HH*GG][TSLOTS];   // (ksign<<32)|idx, linear probing
__device__ int g_cand[BB*HH*SS*KMAX];
__device__ int g_ccount[BB*HH*SS];
__device__ int g_anyflag;
// overflow buffers for the (astronomically rare) many-match fallback path
__device__ int   g_midx[(size_t)BB*HH*SS*1024];
__device__ float g_msc[(size_t)BB*HH*SS*1024];

__device__ __forceinline__ unsigned f2u_ord(float f) {
    unsigned u = __float_as_uint(f);
    return (u & 0x80000000u) ? ~u : (u | 0x80000000u);
}
__device__ __forceinline__ ull ffma2(ull a, ull b, ull c) {
    ull d;
    asm("fma.rn.f32x2 %0, %1, %2, %3;" : "=l"(d) : "l"(a), "l"(b), "l"(c));
    return d;
}
__device__ __forceinline__ ull packf2(float x, float y) {
    ull d;
    asm("mov.b64 %0, {%1, %2};" : "=l"(d) : "f"(x), "f"(y));
    return d;
}
__device__ __forceinline__ void unpackf2(ull v, float& lo, float& hi) {
    asm("mov.b64 {%0, %1}, %2;" : "=f"(lo), "=f"(hi) : "l"(v));
}

// ---------------- K1: fused low-rank projection (+ htab clear) ---------------
// stage1: tmp_tile[64 rows][64 cols] = X_tile @ A_tile (K=512)   (kept in smem)
// stage2: per covered head: out_tile = tmp_h[64x16] @ B_h[16x64]
// grid (2048/64, 128/64, 2{q,k}), 256 thr ; 128 blocks * 256 = 32768 = #slots
__global__ void k_proj(const float* __restrict__ Xq, const float* __restrict__ Xk,
                       const float* __restrict__ Aq, const float* __restrict__ Ak,
                       const float* __restrict__ Bq, const float* __restrict__ Bk) {
    int m0 = blockIdx.x * 64;
    int n0 = blockIdx.y * 64;
    int z = blockIdx.z;
    int tid = threadIdx.x;
    // fold in hash-table clear (k_hash runs strictly after this kernel)
    {
        int lin = ((blockIdx.z * gridDim.y + blockIdx.y) * gridDim.x + blockIdx.x) * 256 + tid;
        ((ull*)g_htab)[lin] = ~0ull;
        if (lin == 0) g_anyflag = 0;
    }
    const float* X  = z ? Xk : Xq;
    const float* Am = z ? Ak : Aq;
    const float* Bm = z ? Bk : Bq;
    float* Out = z ? g_kup : g_qup;
    __shared__ float As[32][66];   // stage1: As[d][row]
    __shared__ float Bs[32][68];   // stage1 B / stage2 B_h (16x68 used)
    __shared__ float Ts[64][68];   // stage1 result tile
    int tx = tid & 15, ty = tid >> 4;
    ull acc[2][4] = {};            // row-pairs x 4 cols, packed f32x2
    for (int d0 = 0; d0 < DD; d0 += 32) {
#pragma unroll
        for (int t = 0; t < 2; t++) {
            int lin = tid + t * 256;
            int r = lin >> 3, d4 = lin & 7;
            float4 v = *(const float4*)&X[(m0 + r) * DD + d0 + d4 * 4];
            As[d4*4+0][r] = v.x; As[d4*4+1][r] = v.y;
            As[d4*4+2][r] = v.z; As[d4*4+3][r] = v.w;
        }
#pragma unroll
        for (int t = 0; t < 2; t++) {
            int lin = tid + t * 256;
            int r = lin >> 4;             // d-row 0..31
            int cc = (lin & 15) * 4;      // col 0..60
            int c = n0 + cc;
            int h = c >> 4, rr = c & 15;
            float4 v = *(const float4*)&Am[h * (DD * RR) + (d0 + r) * RR + rr];
            *(float4*)&Bs[r][cc] = v;
        }
        __syncthreads();
#pragma unroll
        for (int d = 0; d < 32; d++) {
            ull a01 = *(const ull*)&As[d][ty * 4];
            ull a23 = *(const ull*)&As[d][ty * 4 + 2];
            float4 bv = *(const float4*)&Bs[d][tx * 4];
            ull bx = packf2(bv.x, bv.x), by = packf2(bv.y, bv.y);
            ull bz2 = packf2(bv.z, bv.z), bw = packf2(bv.w, bv.w);
            acc[0][0] = ffma2(a01, bx, acc[0][0]);
            acc[0][1] = ffma2(a01, by, acc[0][1]);
            acc[0][2] = ffma2(a01, bz2, acc[0][2]);
            acc[0][3] = ffma2(a01, bw, acc[0][3]);
            acc[1][0] = ffma2(a23, bx, acc[1][0]);
            acc[1][1] = ffma2(a23, by, acc[1][1]);
            acc[1][2] = ffma2(a23, bz2, acc[1][2]);
            acc[1][3] = ffma2(a23, bw, acc[1][3]);
        }
        __syncthreads();
    }
#pragma unroll
    for (int pr = 0; pr < 2; pr++)
#pragma unroll
        for (int j = 0; j < 4; j++) {
            float lo, hi;
            unpackf2(acc[pr][j], lo, hi);
            Ts[ty*4 + pr*2 + 0][tx*4 + j] = lo;
            Ts[ty*4 + pr*2 + 1][tx*4 + j] = hi;
        }
    __syncthreads();
    int b = m0 >> 10;
    int sbase = m0 & (SS - 1);
    int h0 = n0 >> 4;
#pragma unroll
    for (int hl = 0; hl < 4; hl++) {
        int h = h0 + hl;
#pragma unroll
        for (int t = 0; t < 4; t++) {
            int lin = tid + t * 256;
            int kk = lin >> 6, cc = lin & 63;
            Bs[kk][cc] = Bm[h * RR * DKK + kk * DKK + cc];
        }
        __syncthreads();
        float c4[4][4] = {};
#pragma unroll
        for (int kk = 0; kk < 16; kk++) {
            float a0 = Ts[ty*4+0][hl*16+kk], a1 = Ts[ty*4+1][hl*16+kk];
            float a2 = Ts[ty*4+2][hl*16+kk], a3 = Ts[ty*4+3][hl*16+kk];
            float4 bv = *(const float4*)&Bs[kk][tx * 4];
            c4[0][0] += a0*bv.x; c4[0][1] += a0*bv.y; c4[0][2] += a0*bv.z; c4[0][3] += a0*bv.w;
            c4[1][0] += a1*bv.x; c4[1][1] += a1*bv.y; c4[1][2] += a1*bv.z; c4[1][3] += a1*bv.w;
            c4[2][0] += a2*bv.x; c4[2][1] += a2*bv.y; c4[2][2] += a2*bv.z; c4[2][3] += a2*bv.w;
            c4[3][0] += a3*bv.x; c4[3][1] += a3*bv.y; c4[3][2] += a3*bv.z; c4[3][3] += a3*bv.w;
        }
#pragma unroll
        for (int i = 0; i < 4; i++) {
            int s = sbase + ty * 4 + i;
            float4 v = make_float4(c4[i][0], c4[i][1], c4[i][2], c4[i][3]);
            *(float4*)&Out[(((b * HH + h) * SS) + s) * DKK + tx * 4] = v;
        }
        __syncthreads();
    }
}

// ---------------- K2: LSH hashes + sign masks + hash-table build ------------
__global__ void k_hash(const float* __restrict__ lsh) {
    int idx = blockIdx.x * 256 + threadIdx.x;
    if (idx >= BB * HH * GG * SS) return;
    int s = idx & (SS - 1);
    int g = (idx >> 10) & 1;
    int h = (idx >> 11) & 7;
    int b = idx >> 14;
    const float* qr = &g_qup[(((b * HH + h) * SS) + s) * DKK + g * GDD];
    const float* kr = &g_kup[(((b * HH + h) * SS) + s) * DKK + g * GDD];
    const float* pp = &lsh[(h * GG + g) * GDD * NHH];
    float pq[NHH] = {}, pk[NHH] = {};
    unsigned sq = 0u, sk = 0u;
#pragma unroll 8
    for (int d = 0; d < GDD; d++) {
        float qv = qr[d], kv = kr[d];
        if (qv > 0.f) sq |= (1u << d);
        if (kv > 0.f) sk |= (1u << d);
#pragma unroll
        for (int n = 0; n < NHH; n++) {
            float w = pp[d * NHH + n];
            pq[n] += qv * w;
            pk[n] += kv * w;
        }
    }
    unsigned hq = 0u, hk = 0u;
#pragma unroll
    for (int n = 0; n < NHH; n++) {
        int fq = (int)floorf(pq[n] * 0.25f);
        int fk = (int)floorf(pk[n] * 0.25f);
        hq |= ((unsigned)(fq & 63)) << (8 * n);
        hk |= ((unsigned)(fk & 63)) << (8 * n);
    }
    g_hq[idx] = hq;
    g_hk[idx] = hk;
    if (b == BB - 1) {
        int hg = h * GG + g;
        g_qsign[hg * SS + s] = sq;
        ull entry = (((ull)sk) << 32) | (unsigned)s;
        unsigned slot = (sk * 2654435761u) >> 21;   // 11 bits
        while (atomicCAS(&g_htab[hg][slot & (TSLOTS-1)], ~0ull, entry) != ~0ull)
            slot++;
    }
}

// ---------------- K3: candidate generation (warp per row, lazy) -------------
__global__ void k_cand() {
    __shared__ unsigned unionw[4][32];
    __shared__ unsigned gmask[4][32];
    __shared__ int shcnt[4];
    int tid = threadIdx.x, wid = tid >> 5, lane = tid & 31;
    int row = blockIdx.x * 4 + wid;
    int s = row & (SS - 1), h = (row >> 10) & 7, b = row >> 13;
    unionw[wid][lane] = 0u;
    __syncwarp();
    for (int g = 0; g < GG; g++) {
        gmask[wid][lane] = 0u;
        __syncwarp();
        int hg = h * GG + g;
        unsigned qsig = g_qsign[hg * SS + s];
        unsigned hqv = g_hq[((b * HH + h) * GG + g) * SS + s];
        const ull* tab = g_htab[hg];
        const unsigned* hkp = &g_hk[((b * HH + h) * GG + g) * SS];
        unsigned start = (qsig * 2654435761u) >> 21;
        int gcnt = 0;
        for (int w = 0; w < TSLOTS / 32; w++) {
            int p = (start + w * 32 + lane) & (TSLOTS - 1);
            ull e = tab[p];
            bool empty = (e == ~0ull);
            unsigned em = __ballot_sync(0xffffffffu, empty);
            unsigned valid = em ? ((em & (unsigned)(-(int)em)) - 1u) : 0xffffffffu;
            bool mt = false; int j = 0;
            if (!empty && ((valid >> lane) & 1u) && (unsigned)(e >> 32) == qsig) {
                j = (int)(e & 0xffffffffu);
                mt = (__vcmpeq4(hqv, hkp[j]) != 0u);
            }
            unsigned bal = __ballot_sync(0xffffffffu, mt);
            if (mt) atomicOr(&gmask[wid][j >> 5], 1u << (j & 31));
            gcnt += __popc(bal);
            if (em) break;
        }
        if (gcnt > KMAX) {
            // rare fallback: compute scores for flagged j's, exact 64th-largest
            const float* qbase = &g_qup[row * DKK + g * GDD];
            const float* kbase = &g_kup[(b * HH + h) * SS * DKK + g * GDD];
            int* mix = &g_midx[(size_t)row * 1024];
            float* msf = &g_msc[(size_t)row * 1024];
            if (lane == 0) shcnt[wid] = 0;
            __syncwarp();
            unsigned w = gmask[wid][lane];
            while (w) {
                int bpos = __ffs(w) - 1;
                w &= w - 1;
                int j = lane * 32 + bpos;
                float a = 0.f;
                const float* kr = kbase + j * DKK;
#pragma unroll
                for (int d = 0; d < GDD; d++) a += qbase[d] * kr[d];
                int rk = atomicAdd(&shcnt[wid], 1);
                mix[rk] = j; msf[rk] = a;
            }
            __syncwarp();
            gmask[wid][lane] = 0u;
            __syncwarp();
            unsigned prefix = 0u; int kk = KMAX;
            for (int bit = 31; bit >= 0; bit--) {
                int local = 0;
                for (int i = lane; i < gcnt; i += 32) {
                    unsigned key = f2u_ord(msf[i]);
                    unsigned hi2 = (bit == 31) ? 0u : (key >> (bit + 1));
                    if (hi2 == prefix && ((key >> bit) & 1u)) local++;
                }
#pragma unroll
                for (int off = 16; off; off >>= 1) local += __shfl_xor_sync(0xffffffffu, local, off);
                if (local >= kk) prefix = (prefix << 1) | 1u;
                else { kk -= local; prefix <<= 1; }
            }
            for (int i = lane; i < gcnt; i += 32)
                if (f2u_ord(msf[i]) >= prefix)
                    atomicOr(&gmask[wid][mix[i] >> 5], 1u << (mix[i] & 31));
        }
        __syncwarp();
        unionw[wid][lane] |= gmask[wid][lane];
        __syncwarp();
    }
    unsigned w = unionw[wid][lane];
    int c = __popc(w);
    int pre = c;
#pragma unroll
    for (int off = 1; off < 32; off <<= 1) {
        int n = __shfl_up_sync(0xffffffffu, pre, off);
        if (lane >= off) pre += n;
    }
    int excl = pre - c;
    int total = __shfl_sync(0xffffffffu, pre, 31);
    if (lane == 0) g_ccount[row] = (total > KMAX) ? KMAX : total;
    if (total > 0) {
        int* crow = &g_cand[row * KMAX];
        int rank = excl;
        while (w && rank < KMAX) {
            int bpos = __ffs(w) - 1;
            w &= w - 1;
            crow[rank++] = lane * 32 + bpos;
        }
        if (lane == 0) atomicAdd(&g_anyflag, 1);
    }
}

// ---------------- K4: v_up = value @ Wv (guarded fallback) ------------------
__global__ void k_vup(const float* __restrict__ value, const float* __restrict__ Wv) {
    if (g_anyflag == 0) return;  // vup only consumed via candidates
    int s0 = blockIdx.x * 64;
    int h = blockIdx.y, b = blockIdx.z;
    __shared__ float As[64][32];
    __shared__ float Bs[32][64];
    int tid = threadIdx.x;
    int tx = tid & 15, ty = tid >> 4;
    float c[4][4] = {};
    for (int d0 = 0; d0 < DD; d0 += 32) {
        for (int i = tid; i < 64 * 32; i += 256) {
            int r = i >> 5, cc = i & 31;
            As[r][cc] = value[(b * SS + s0 + r) * DD + d0 + cc];
        }
        for (int i = tid; i < 32 * 64; i += 256) {
            int r = i >> 6, cc = i & 63;
            Bs[r][cc] = Wv[h * DD * DKK + (d0 + r) * DKK + cc];
        }
        __syncthreads();
#pragma unroll 8
        for (int d = 0; d < 32; d++) {
            float a0 = As[ty*4+0][d], a1 = As[ty*4+1][d];
            float a2 = As[ty*4+2][d], a3 = As[ty*4+3][d];
            float4 bv = *(const float4*)&Bs[d][tx * 4];
            c[0][0] += a0*bv.x; c[0][1] += a0*bv.y; c[0][2] += a0*bv.z; c[0][3] += a0*bv.w;
            c[1][0] += a1*bv.x; c[1][1] += a1*bv.y; c[1][2] += a1*bv.z; c[1][3] += a1*bv.w;
            c[2][0] += a2*bv.x; c[2][1] += a2*bv.y; c[2][2] += a2*bv.z; c[2][3] += a2*bv.w;
            c[3][0] += a3*bv.x; c[3][1] += a3*bv.y; c[3][2] += a3*bv.z; c[3][3] += a3*bv.w;
        }
        __syncthreads();
    }
    for (int i = 0; i < 4; i++) {
        int r = ty * 4 + i;
        float4 v = make_float4(c[i][0], c[i][1], c[i][2], c[i][3]);
        *(float4*)&g_vup[(((b * HH + h) * SS) + s0 + r) * DKK + tx * 4] = v;
    }
}

// ---------------- K5: sparse attention over candidates ----------------------
__global__ void k_attn() {
    if (g_anyflag == 0) return;  // outh unused when no candidates anywhere
    int wl = threadIdx.x >> 5;
    int lane = threadIdx.x & 31;
    int rid = blockIdx.x * 4 + wl;
    __shared__ float sq[4][DKK];
    __shared__ int sj[4][KMAX];
    __shared__ float sp[4][KMAX];
    int cnt = g_ccount[rid];
    const float* qr = &g_qup[rid * DKK];
    sq[wl][lane] = qr[lane];
    sq[wl][lane + 32] = qr[lane + 32];
    const int* crow = &g_cand[rid * KMAX];
    sj[wl][lane]      = (lane      < cnt) ? crow[lane]      : -1;
    sj[wl][lane + 32] = (lane + 32 < cnt) ? crow[lane + 32] : -1;
    __syncwarp();
    int base = (rid & ~(SS - 1)) * DKK;
    const float* kb = &g_kup[base];
    float l0 = NEGF, l1 = NEGF;
    int j0 = sj[wl][lane], j1 = sj[wl][lane + 32];
    if (j0 >= 0) {
        const float* kr = kb + j0 * DKK;
        float a = 0.f;
#pragma unroll
        for (int d = 0; d < DKK; d++) a += sq[wl][d] * kr[d];
        l0 = a * 0.125f;
    }
    if (j1 >= 0) {
        const float* kr = kb + j1 * DKK;
        float a = 0.f;
#pragma unroll
        for (int d = 0; d < DKK; d++) a += sq[wl][d] * kr[d];
        l1 = a * 0.125f;
    }
    float mx = fmaxf(l0, l1);
#pragma unroll
    for (int off = 16; off; off >>= 1) mx = fmaxf(mx, __shfl_xor_sync(0xffffffffu, mx, off));
    float e0 = (j0 >= 0) ? expf(l0 - mx) : 0.f;
    float e1 = (j1 >= 0) ? expf(l1 - mx) : 0.f;
    float ssum = e0 + e1;
#pragma unroll
    for (int off = 16; off; off >>= 1) ssum += __shfl_xor_sync(0xffffffffu, ssum, off);
    float inv = (ssum > 0.f) ? (1.f / ssum) : 0.f;
    sp[wl][lane] = e0 * inv;
    sp[wl][lane + 32] = e1 * inv;
    __syncwarp();
    const float* vb = &g_vup[base];
    float o0 = 0.f, o1 = 0.f;
    for (int c = 0; c < cnt; c++) {
        int j = sj[wl][c];
        if (j < 0) break;
        float p = sp[wl][c];
        const float* vr = vb + j * DKK;
        o0 += p * vr[lane];
        o1 += p * vr[lane + 32];
    }
    g_outh[rid * DKK + lane] = o0;
    g_outh[rid * DKK + lane + 32] = o1;
}

// ---------------- K6: output projection (guarded zero-fill) -----------------
__global__ void k_out(const float* __restrict__ Wo, float* __restrict__ out) {
    int s0 = blockIdx.x * 64;
    int n0 = blockIdx.y * 64;
    int b = blockIdx.z;
    int tid = threadIdx.x;
    int tx = tid & 15, ty = tid >> 4;
    if (g_anyflag == 0) {
        float4 z = make_float4(0.f, 0.f, 0.f, 0.f);
#pragma unroll
        for (int i = 0; i < 4; i++) {
            int r = ty * 4 + i;
            *(float4*)&out[(b * SS + s0 + r) * DD + n0 + tx * 4] = z;
        }
        return;
    }
    __shared__ float As[64][32];
    __shared__ float Bs[32][64];
    float c[4][4] = {};
    for (int c0 = 0; c0 < HH * DKK; c0 += 32) {
        int h = c0 >> 6;
        int kbase = c0 & 63;
        for (int i = tid; i < 64 * 32; i += 256) {
            int r = i >> 5, cc = i & 31;
            As[r][cc] = g_outh[(((b * HH + h) * SS) + s0 + r) * DKK + kbase + cc];
        }
        for (int i = tid; i < 32 * 64; i += 256) {
            int r = i >> 6, cc = i & 63;
            Bs[r][cc] = Wo[(c0 + r) * DD + n0 + cc];
        }
        __syncthreads();
#pragma unroll 8
        for (int d = 0; d < 32; d++) {
            float a0 = As[ty*4+0][d], a1 = As[ty*4+1][d];
            float a2 = As[ty*4+2][d], a3 = As[ty*4+3][d];
            float4 bv = *(const float4*)&Bs[d][tx * 4];
            c[0][0] += a0*bv.x; c[0][1] += a0*bv.y; c[0][2] += a0*bv.z; c[0][3] += a0*bv.w;
            c[1][0] += a1*bv.x; c[1][1] += a1*bv.y; c[1][2] += a1*bv.z; c[1][3] += a1*bv.w;
            c[2][0] += a2*bv.x; c[2][1] += a2*bv.y; c[2][2] += a2*bv.z; c[2][3] += a2*bv.w;
            c[3][0] += a3*bv.x; c[3][1] += a3*bv.y; c[3][2] += a3*bv.z; c[3][3] += a3*bv.w;
        }
        __syncthreads();
    }
    for (int i = 0; i < 4; i++) {
        int r = ty * 4 + i;
        float4 v = make_float4(c[i][0], c[i][1], c[i][2], c[i][3]);
        *(float4*)&out[(b * SS + s0 + r) * DD + n0 + tx * 4] = v;
    }
}

// ---------------- launch ----------------------------------------------------
extern "C" void kernel_launch(void* const* d_in, const int* in_sizes, int n_in,
                              void* d_out, int out_size) {
    const float* query = (const float*)d_in[0];
    const float* key   = (const float*)d_in[1];
    const float* value = (const float*)d_in[2];
    const float* Aq    = (const float*)d_in[3];
    const float* Bq    = (const float*)d_in[4];
    const float* Ak    = (const float*)d_in[5];
    const float* Bk    = (const float*)d_in[6];
    const float* Wv    = (const float*)d_in[7];
    const float* Wo    = (const float*)d_in[8];
    const float* lsh   = (const float*)d_in[9];
    float* out = (float*)d_out;

    k_proj<<<dim3(BB * SS / 64, (HH * RR) / 64, 2), 256>>>(query, key, Aq, Ak, Bq, Bk);
    k_hash<<<(BB * HH * GG * SS + 255) / 256, 256>>>(lsh);
    k_cand<<<BB * HH * SS / 4, 128>>>();
    k_vup<<<dim3(SS / 64, HH, BB), 256>>>(value, Wv);
    k_attn<<<BB * HH * SS / 4, 128>>>();
    k_out<<<dim3(SS / 64, DD / 64, BB), 256>>>(Wo, out);
}

// round 5
// speedup vs baseline: 4.5788x; 1.0334x over previous
#include <cuda_runtime.h>
#include <cuda_bf16.h>
#include <stdint.h>

#define BB 2
#define SS 1024
#define DD 512
#define HH 8
#define DKK 64
#define RR 16
#define GG 2
#define GDD 32
#define NHH 4
#define KMAX 64
#define NEGF (-1e30f)
#define TSLOTS 2048

typedef unsigned long long ull;

// ---------------- scratch (device globals; no allocation allowed) ----------
// NOTE: g_htab empty marker is 0 (matches zero-init at module load); k_epi
// re-clears it at the end of every call so each replay starts empty.
__device__ float g_qup[BB*HH*SS*DKK];   // [b][h][s][k]
__device__ float g_kup[BB*HH*SS*DKK];
__device__ unsigned g_hq[BB*HH*GG*SS];  // packed 4 hash bytes
__device__ unsigned g_hk[BB*HH*GG*SS];
__device__ unsigned g_qsign[HH*GG*SS];  // q sign masks from batch B-1
__device__ ull g_htab[HH*GG][TSLOTS];   // (ksign<<32)|0x80000000|idx; 0=empty
__device__ int g_cand[BB*HH*SS*KMAX];
__device__ int g_ccount[BB*HH*SS];
// overflow buffers for the (astronomically rare) many-match fallback path
__device__ int   g_midx[(size_t)BB*HH*SS*1024];
__device__ float g_msc[(size_t)BB*HH*SS*1024];

__device__ __forceinline__ unsigned f2u_ord(float f) {
    unsigned u = __float_as_uint(f);
    return (u & 0x80000000u) ? ~u : (u | 0x80000000u);
}
__device__ __forceinline__ ull ffma2(ull a, ull b, ull c) {
    ull d;
    asm("fma.rn.f32x2 %0, %1, %2, %3;" : "=l"(d) : "l"(a), "l"(b), "l"(c));
    return d;
}
__device__ __forceinline__ ull packf2(float x, float y) {
    ull d;
    asm("mov.b64 %0, {%1, %2};" : "=l"(d) : "f"(x), "f"(y));
    return d;
}
__device__ __forceinline__ void unpackf2(ull v, float& lo, float& hi) {
    asm("mov.b64 {%0, %1}, %2;" : "=f"(lo), "=f"(hi) : "l"(v));
}

// ---------------- A: fused low-rank projection + hash/sign/insert -----------
// stage1: tmp_tile[64 rows][64 cols] = X_tile @ A_tile (K=512)  (kept in smem)
// stage2: per covered head: out_tile = tmp_h[64x16] @ B_h[16x64] -> global
// stage3: hash + sign masks for the tile's (h,g,s) items, htab insert (z=1,b=1)
// grid (2048/64, 128/64, 2{q,k}), 256 thr
__global__ void k_proj(const float* __restrict__ Xq, const float* __restrict__ Xk,
                       const float* __restrict__ Aq, const float* __restrict__ Ak,
                       const float* __restrict__ Bq, const float* __restrict__ Bk,
                       const float* __restrict__ lsh) {
    int m0 = blockIdx.x * 64;
    int n0 = blockIdx.y * 64;
    int z = blockIdx.z;
    int tid = threadIdx.x;
    const float* X  = z ? Xk : Xq;
    const float* Am = z ? Ak : Aq;
    const float* Bm = z ? Bk : Bq;
    float* Out = z ? g_kup : g_qup;
    __shared__ float As[32][66];   // stage1: As[d][row]
    __shared__ float Bs[32][68];   // stage1 B / stage2 B_h (16x68 used)
    __shared__ float Ts[64][68];   // stage1 result tile
    int tx = tid & 15, ty = tid >> 4;
    ull acc[2][4] = {};            // row-pairs x 4 cols, packed f32x2
    for (int d0 = 0; d0 < DD; d0 += 32) {
#pragma unroll
        for (int t = 0; t < 2; t++) {
            int lin = tid + t * 256;
            int r = lin >> 3, d4 = lin & 7;
            float4 v = *(const float4*)&X[(m0 + r) * DD + d0 + d4 * 4];
            As[d4*4+0][r] = v.x; As[d4*4+1][r] = v.y;
            As[d4*4+2][r] = v.z; As[d4*4+3][r] = v.w;
        }
#pragma unroll
        for (int t = 0; t < 2; t++) {
            int lin = tid + t * 256;
            int r = lin >> 4;
            int cc = (lin & 15) * 4;
            int c = n0 + cc;
            int h = c >> 4, rr = c & 15;
            float4 v = *(const float4*)&Am[h * (DD * RR) + (d0 + r) * RR + rr];
            *(float4*)&Bs[r][cc] = v;
        }
        __syncthreads();
#pragma unroll
        for (int d = 0; d < 32; d++) {
            ull a01 = *(const ull*)&As[d][ty * 4];
            ull a23 = *(const ull*)&As[d][ty * 4 + 2];
            float4 bv = *(const float4*)&Bs[d][tx * 4];
            ull bx = packf2(bv.x, bv.x), by = packf2(bv.y, bv.y);
            ull bz2 = packf2(bv.z, bv.z), bw = packf2(bv.w, bv.w);
            acc[0][0] = ffma2(a01, bx, acc[0][0]);
            acc[0][1] = ffma2(a01, by, acc[0][1]);
            acc[0][2] = ffma2(a01, bz2, acc[0][2]);
            acc[0][3] = ffma2(a01, bw, acc[0][3]);
            acc[1][0] = ffma2(a23, bx, acc[1][0]);
            acc[1][1] = ffma2(a23, by, acc[1][1]);
            acc[1][2] = ffma2(a23, bz2, acc[1][2]);
            acc[1][3] = ffma2(a23, bw, acc[1][3]);
        }
        __syncthreads();
    }
#pragma unroll
    for (int pr = 0; pr < 2; pr++)
#pragma unroll
        for (int j = 0; j < 4; j++) {
            float lo, hi;
            unpackf2(acc[pr][j], lo, hi);
            Ts[ty*4 + pr*2 + 0][tx*4 + j] = lo;
            Ts[ty*4 + pr*2 + 1][tx*4 + j] = hi;
        }
    __syncthreads();
    int b = m0 >> 10;
    int sbase = m0 & (SS - 1);
    int h0 = n0 >> 4;
#pragma unroll
    for (int hl = 0; hl < 4; hl++) {
        int h = h0 + hl;
#pragma unroll
        for (int t = 0; t < 4; t++) {
            int lin = tid + t * 256;
            int kk = lin >> 6, cc = lin & 63;
            Bs[kk][cc] = Bm[h * RR * DKK + kk * DKK + cc];
        }
        __syncthreads();
        float c4[4][4] = {};
#pragma unroll
        for (int kk = 0; kk < 16; kk++) {
            float a0 = Ts[ty*4+0][hl*16+kk], a1 = Ts[ty*4+1][hl*16+kk];
            float a2 = Ts[ty*4+2][hl*16+kk], a3 = Ts[ty*4+3][hl*16+kk];
            float4 bv = *(const float4*)&Bs[kk][tx * 4];
            c4[0][0] += a0*bv.x; c4[0][1] += a0*bv.y; c4[0][2] += a0*bv.z; c4[0][3] += a0*bv.w;
            c4[1][0] += a1*bv.x; c4[1][1] += a1*bv.y; c4[1][2] += a1*bv.z; c4[1][3] += a1*bv.w;
            c4[2][0] += a2*bv.x; c4[2][1] += a2*bv.y; c4[2][2] += a2*bv.z; c4[2][3] += a2*bv.w;
            c4[3][0] += a3*bv.x; c4[3][1] += a3*bv.y; c4[3][2] += a3*bv.z; c4[3][3] += a3*bv.w;
        }
#pragma unroll
        for (int i = 0; i < 4; i++) {
            int s = sbase + ty * 4 + i;
            float4 v = make_float4(c4[i][0], c4[i][1], c4[i][2], c4[i][3]);
            *(float4*)&Out[(((b * HH + h) * SS) + s) * DKK + tx * 4] = v;
        }
        __syncthreads();
    }
    // ---- stage3: hash + signs from just-written tile (L1-hot) ----
#pragma unroll
    for (int t = 0; t < 2; t++) {
        int item = tid + t * 256;        // 512 = 4 heads x 2 groups x 64 rows
        int hl = item >> 7, rem = item & 127;
        int g = rem >> 6, r = rem & 63;
        int h = h0 + hl, s = sbase + r;
        const float* rowp = &Out[(((b*HH + h) * SS) + s) * DKK + g * GDD];
        const float4* pr = (const float4*)&lsh[(h * GG + g) * GDD * NHH];
        float a0 = 0.f, a1 = 0.f, a2 = 0.f, a3 = 0.f;
        unsigned sg = 0u;
#pragma unroll
        for (int d = 0; d < GDD; d++) {
            float v = rowp[d];
            float4 p = pr[d];
            if (v > 0.f) sg |= (1u << d);
            a0 += v * p.x; a1 += v * p.y; a2 += v * p.z; a3 += v * p.w;
        }
        unsigned hw = ((unsigned)(((int)floorf(a0 * 0.25f)) & 63))
                    | ((unsigned)(((int)floorf(a1 * 0.25f)) & 63) << 8)
                    | ((unsigned)(((int)floorf(a2 * 0.25f)) & 63) << 16)
                    | ((unsigned)(((int)floorf(a3 * 0.25f)) & 63) << 24);
        int idx = ((b * HH + h) * GG + g) * SS + s;
        if (z == 0) {
            g_hq[idx] = hw;
            if (b == BB - 1) g_qsign[(h * GG + g) * SS + s] = sg;
        } else {
            g_hk[idx] = hw;
            if (b == BB - 1) {
                ull entry = (((ull)sg) << 32) | 0x80000000u | (unsigned)s;
                unsigned slot = (sg * 2654435761u) >> 21;
                while (atomicCAS(&g_htab[h * GG + g][slot & (TSLOTS - 1)], 0ull, entry) != 0ull)
                    slot++;
            }
        }
    }
}

// ---------------- B: candidate generation (warp per row, lazy) --------------
__global__ void k_cand() {
    __shared__ unsigned unionw[4][32];
    __shared__ unsigned gmask[4][32];
    __shared__ int shcnt[4];
    int tid = threadIdx.x, wid = tid >> 5, lane = tid & 31;
    int row = blockIdx.x * 4 + wid;
    int s = row & (SS - 1), h = (row >> 10) & 7, b = row >> 13;
    unionw[wid][lane] = 0u;
    __syncwarp();
    for (int g = 0; g < GG; g++) {
        gmask[wid][lane] = 0u;
        __syncwarp();
        int hg = h * GG + g;
        unsigned qsig = g_qsign[hg * SS + s];
        unsigned hqv = g_hq[((b * HH + h) * GG + g) * SS + s];
        const ull* tab = g_htab[hg];
        const unsigned* hkp = &g_hk[((b * HH + h) * GG + g) * SS];
        unsigned start = (qsig * 2654435761u) >> 21;
        int gcnt = 0;
        for (int w = 0; w < TSLOTS / 32; w++) {
            int p = (start + w * 32 + lane) & (TSLOTS - 1);
            ull e = tab[p];
            bool empty = (e == 0ull);
            unsigned em = __ballot_sync(0xffffffffu, empty);
            unsigned valid = em ? ((em & (unsigned)(-(int)em)) - 1u) : 0xffffffffu;
            bool mt = false; int j = 0;
            if (!empty && ((valid >> lane) & 1u) && (unsigned)(e >> 32) == qsig) {
                j = (int)(e & 0x3FFu);
                mt = (__vcmpeq4(hqv, hkp[j]) != 0u);
            }
            unsigned bal = __ballot_sync(0xffffffffu, mt);
            if (mt) atomicOr(&gmask[wid][j >> 5], 1u << (j & 31));
            gcnt += __popc(bal);
            if (em) break;
        }
        if (gcnt > KMAX) {
            // rare fallback: compute scores for flagged j's, exact 64th-largest
            const float* qbase = &g_qup[row * DKK + g * GDD];
            const float* kbase = &g_kup[(b * HH + h) * SS * DKK + g * GDD];
            int* mix = &g_midx[(size_t)row * 1024];
            float* msf = &g_msc[(size_t)row * 1024];
            if (lane == 0) shcnt[wid] = 0;
            __syncwarp();
            unsigned w = gmask[wid][lane];
            while (w) {
                int bpos = __ffs(w) - 1;
                w &= w - 1;
                int j = lane * 32 + bpos;
                float a = 0.f;
                const float* kr = kbase + j * DKK;
#pragma unroll
                for (int d = 0; d < GDD; d++) a += qbase[d] * kr[d];
                int rk = atomicAdd(&shcnt[wid], 1);
                mix[rk] = j; msf[rk] = a;
            }
            __syncwarp();
            gmask[wid][lane] = 0u;
            __syncwarp();
            unsigned prefix = 0u; int kk = KMAX;
            for (int bit = 31; bit >= 0; bit--) {
                int local = 0;
                for (int i = lane; i < gcnt; i += 32) {
                    unsigned key = f2u_ord(msf[i]);
                    unsigned hi2 = (bit == 31) ? 0u : (key >> (bit + 1));
                    if (hi2 == prefix && ((key >> bit) & 1u)) local++;
                }
#pragma unroll
                for (int off = 16; off; off >>= 1) local += __shfl_xor_sync(0xffffffffu, local, off);
                if (local >= kk) prefix = (prefix << 1) | 1u;
                else { kk -= local; prefix <<= 1; }
            }
            for (int i = lane; i < gcnt; i += 32)
                if (f2u_ord(msf[i]) >= prefix)
                    atomicOr(&gmask[wid][mix[i] >> 5], 1u << (mix[i] & 31));
        }
        __syncwarp();
        unionw[wid][lane] |= gmask[wid][lane];
        __syncwarp();
    }
    unsigned w = unionw[wid][lane];
    int c = __popc(w);
    int pre = c;
#pragma unroll
    for (int off = 1; off < 32; off <<= 1) {
        int n = __shfl_up_sync(0xffffffffu, pre, off);
        if (lane >= off) pre += n;
    }
    int excl = pre - c;
    int total = __shfl_sync(0xffffffffu, pre, 31);
    if (lane == 0) g_ccount[row] = (total > KMAX) ? KMAX : total;
    if (total > 0) {
        int* crow = &g_cand[row * KMAX];
        int rank = excl;
        while (w && rank < KMAX) {
            int bpos = __ffs(w) - 1;
            w &= w - 1;
            crow[rank++] = lane * 32 + bpos;
        }
    }
}

// ---------------- C: epilogue (zero-fill fast path; full fallback) -----------
// grid (S/64, DD/64, B), 256 thr. Per block: check its 512 row counts;
// all-zero -> zero out tile. Else compute attn (vup on the fly) + out proj.
// Also clears g_htab for the next call.
__global__ void k_epi(const float* __restrict__ value, const float* __restrict__ Wv,
                      const float* __restrict__ Wo, float* __restrict__ out) {
    int stile = blockIdx.x, ntile = blockIdx.y, b = blockIdx.z;
    int sbase = stile * 64, n0 = ntile * 64;
    int tid = threadIdx.x;
    __shared__ int nzflag;
    if (tid == 0) nzflag = 0;
    __syncthreads();
    int any = 0;
#pragma unroll
    for (int t = 0; t < 2; t++) {
        int item = tid + t * 256;       // 512 = 8 heads x 64 rows
        int h = item >> 6, r = item & 63;
        if (g_ccount[(b * HH + h) * SS + sbase + r] > 0) any = 1;
    }
    if (any) atomicOr(&nzflag, 1);
    // clear htab for next call (nothing reads it after k_cand)
    {
        int lin = ((b * gridDim.y + ntile) * gridDim.x + stile) * 256 + tid;
        if (lin < HH * GG * TSLOTS) ((ull*)g_htab)[lin] = 0ull;
    }
    __syncthreads();
    if (!nzflag) {
        float4 z4 = make_float4(0.f, 0.f, 0.f, 0.f);
#pragma unroll
        for (int t = 0; t < 4; t++) {
            int lin = tid + t * 256;    // 1024 float4 = 64 rows x 16
            int r = lin >> 4, c4i = lin & 15;
            *(float4*)&out[(b * SS + sbase + r) * DD + n0 + c4i * 4] = z4;
        }
        return;
    }
    // ---------- fallback: full sparse attention + output projection ----------
    __shared__ float Oh[64][65];
    __shared__ float Ws[64][65];
    __shared__ float sl[8][KMAX];
    int lane = tid & 31, w = tid >> 5;
    int tx = tid & 15, ty = tid >> 4;
    float acc[4][4] = {};
    for (int h = 0; h < HH; h++) {
        for (int rr = 0; rr < 8; rr++) {
            int r = w * 8 + rr;
            int row = (b * HH + h) * SS + sbase + r;
            int cnt = g_ccount[row];
            float o0 = 0.f, o1 = 0.f;
            if (cnt > 0) {
                const int* crow = &g_cand[row * KMAX];
                const float* q = &g_qup[row * DKK];
                const float* kb2 = &g_kup[(b * HH + h) * SS * DKK];
                float mx = NEGF;
                for (int c = 0; c < cnt; c++) {
                    int j = crow[c];
                    const float* kr = kb2 + j * DKK;
                    float a = q[lane] * kr[lane] + q[lane + 32] * kr[lane + 32];
#pragma unroll
                    for (int off = 16; off; off >>= 1) a += __shfl_xor_sync(0xffffffffu, a, off);
                    a *= 0.125f;
                    if (lane == 0) sl[w][c] = a;
                    mx = fmaxf(mx, a);
                }
                __syncwarp();
                float sum = 0.f;
                for (int c = 0; c < cnt; c++) {
                    float e = expf(sl[w][c] - mx);
                    sum += e;
                }
                __syncwarp();
                float inv = (sum > 0.f) ? (1.f / sum) : 0.f;
                for (int c = 0; c < cnt; c++) {
                    int j = crow[c];
                    float p = expf(sl[w][c] - mx) * inv;
                    const float* vr = &value[(b * SS + j) * DD];
                    const float* wv = &Wv[h * DD * DKK];
                    float v0 = 0.f, v1 = 0.f;
                    for (int d = 0; d < DD; d++) {
                        float vv = vr[d];
                        v0 += vv * wv[d * DKK + lane];
                        v1 += vv * wv[d * DKK + lane + 32];
                    }
                    o0 += p * v0; o1 += p * v1;
                }
            }
            Oh[r][lane] = o0; Oh[r][lane + 32] = o1;
        }
        __syncthreads();
#pragma unroll
        for (int t = 0; t < 16; t++) {
            int lin = tid + t * 256;    // 4096 = 64x64
            int kk = lin >> 6, cc = lin & 63;
            Ws[kk][cc] = Wo[(h * DKK + kk) * DD + n0 + cc];
        }
        __syncthreads();
        for (int kk = 0; kk < DKK; kk++) {
            float a0 = Oh[ty*4+0][kk], a1 = Oh[ty*4+1][kk];
            float a2 = Oh[ty*4+2][kk], a3 = Oh[ty*4+3][kk];
            float b0 = Ws[kk][tx*4+0], b1 = Ws[kk][tx*4+1];
            float b2 = Ws[kk][tx*4+2], b3 = Ws[kk][tx*4+3];
            acc[0][0] += a0*b0; acc[0][1] += a0*b1; acc[0][2] += a0*b2; acc[0][3] += a0*b3;
            acc[1][0] += a1*b0; acc[1][1] += a1*b1; acc[1][2] += a1*b2; acc[1][3] += a1*b3;
            acc[2][0] += a2*b0; acc[2][1] += a2*b1; acc[2][2] += a2*b2; acc[2][3] += a2*b3;
            acc[3][0] += a3*b0; acc[3][1] += a3*b1; acc[3][2] += a3*b2; acc[3][3] += a3*b3;
        }
        __syncthreads();
    }
#pragma unroll
    for (int i = 0; i < 4; i++) {
        float4 v = make_float4(acc[i][0], acc[i][1], acc[i][2], acc[i][3]);
        *(float4*)&out[(b * SS + sbase + ty * 4 + i) * DD + n0 + tx * 4] = v;
    }
}

// ---------------- launch ----------------------------------------------------
extern "C" void kernel_launch(void* const* d_in, const int* in_sizes, int n_in,
                              void* d_out, int out_size) {
    const float* query = (const float*)d_in[0];
    const float* key   = (const float*)d_in[1];
    const float* value = (const float*)d_in[2];
    const float* Aq    = (const float*)d_in[3];
    const float* Bq    = (const float*)d_in[4];
    const float* Ak    = (const float*)d_in[5];
    const float* Bk    = (const float*)d_in[6];
    const float* Wv    = (const float*)d_in[7];
    const float* Wo    = (const float*)d_in[8];
    const float* lsh   = (const float*)d_in[9];
    float* out = (float*)d_out;

    k_proj<<<dim3(BB * SS / 64, (HH * RR) / 64, 2), 256>>>(query, key, Aq, Ak, Bq, Bk, lsh);
    k_cand<<<BB * HH * SS / 4, 128>>>();
    k_epi<<<dim3(SS / 64, DD / 64, BB), 256>>>(value, Wv, Wo, out);
}